// round 1
// baseline (speedup 1.0000x reference)
#include <cuda_runtime.h>
#include <cuda_bf16.h>

// Problem constants (from reference): B=64, W=32 -> BW=2048 blocks
//   query  [S=128, D=64]  fp32 (shared across all bw)
//   keys   [BW, T=256, D=64] fp32
//   values [BW, T=256, D=64] fp32
//   out    [BW, S=128, D=64] fp32
#define S_DIM   128
#define D_DIM   64
#define T_DIM   256
#define T_TILE  64
#define N_TILES (T_DIM / T_TILE)
#define THREADS 256

// Shared-memory pitches (floats), chosen for conflict-free access + 16B alignment
#define SP_PITCH 257   // P rows: scalar access, (s+t)%32 distinct per warp
#define SQ_PITCH 132   // Q^T rows: float4-aligned (132 % 4 == 0)
#define SK_PITCH 68    // K^T / V rows: float4-aligned (68 % 4 == 0)

#define SP_FLOATS  (S_DIM * SP_PITCH)     // 32896
#define SQ_FLOATS  (D_DIM * SQ_PITCH)     // 8448
#define SKV_FLOATS (T_TILE * SK_PITCH)    // 4352
#define SMEM_FLOATS (SP_FLOATS + SQ_FLOATS + SKV_FLOATS)   // 45696
#define SMEM_BYTES  (SMEM_FLOATS * 4)                      // 182784 B

__global__ void __launch_bounds__(THREADS, 1)
attention_encoder_kernel(const float* __restrict__ q,
                         const float* __restrict__ keys,
                         const float* __restrict__ values,
                         float* __restrict__ out)
{
    extern __shared__ float smem[];
    float* sP  = smem;                    // [S_DIM][SP_PITCH]  logits -> probs
    float* sQt = smem + SP_FLOATS;        // [D_DIM][SQ_PITCH]  Q transposed (d-major)
    float* sKV = sQt + SQ_FLOATS;         // [T_TILE][SK_PITCH] K^T tile, then V tile

    const int tid = threadIdx.x;
    const int bw  = blockIdx.x;
    const float* kbase = keys   + (size_t)bw * T_DIM * D_DIM;
    const float* vbase = values + (size_t)bw * T_DIM * D_DIM;

    // ---- Load Q transposed: q[s][d] -> sQt[d][s] --------------------------
    {
        const float4* q4 = (const float4*)q;
        for (int i = tid; i < S_DIM * (D_DIM / 4); i += THREADS) {
            int s  = i >> 4;          // 16 float4 per row
            int c4 = i & 15;
            float4 v = q4[i];
            int d = c4 * 4;
            sQt[(d + 0) * SQ_PITCH + s] = v.x;
            sQt[(d + 1) * SQ_PITCH + s] = v.y;
            sQt[(d + 2) * SQ_PITCH + s] = v.z;
            sQt[(d + 3) * SQ_PITCH + s] = v.w;
        }
    }
    __syncthreads();

    const int sg = tid >> 4;     // 0..15 : s-group
    const int tg = tid & 15;     // 0..15 : t-group (phase1) / d-group (phase3)
    const int s0 = sg * 8;

    // ======================= Phase 1: P = Q @ K^T ==========================
    for (int tile = 0; tile < N_TILES; ++tile) {
        const int t0 = tile * T_TILE;

        // Load K tile transposed: keys[t0+tt][d] -> sKV[d][tt]
        const float4* k4 = (const float4*)(kbase + (size_t)t0 * D_DIM);
        for (int i = tid; i < T_TILE * (D_DIM / 4); i += THREADS) {
            int tt = i >> 4;
            int c4 = i & 15;
            float4 v = k4[i];
            int d = c4 * 4;
            sKV[(d + 0) * SK_PITCH + tt] = v.x;
            sKV[(d + 1) * SK_PITCH + tt] = v.y;
            sKV[(d + 2) * SK_PITCH + tt] = v.z;
            sKV[(d + 3) * SK_PITCH + tt] = v.w;
        }
        __syncthreads();

        // 8(s) x 4(t) register tile, K-dim = D_DIM
        float acc[8][4];
        #pragma unroll
        for (int j = 0; j < 8; ++j)
            #pragma unroll
            for (int i = 0; i < 4; ++i) acc[j][i] = 0.0f;

        #pragma unroll 4
        for (int k = 0; k < D_DIM; ++k) {
            float4 a0 = *(const float4*)&sQt[k * SQ_PITCH + s0];
            float4 a1 = *(const float4*)&sQt[k * SQ_PITCH + s0 + 4];
            float4 b  = *(const float4*)&sKV[k * SK_PITCH + tg * 4];
            float a[8] = {a0.x, a0.y, a0.z, a0.w, a1.x, a1.y, a1.z, a1.w};
            float bb[4] = {b.x, b.y, b.z, b.w};
            #pragma unroll
            for (int j = 0; j < 8; ++j)
                #pragma unroll
                for (int i = 0; i < 4; ++i)
                    acc[j][i] = fmaf(a[j], bb[i], acc[j][i]);
        }

        #pragma unroll
        for (int j = 0; j < 8; ++j)
            #pragma unroll
            for (int i = 0; i < 4; ++i)
                sP[(s0 + j) * SP_PITCH + t0 + tg * 4 + i] = acc[j][i];
        __syncthreads();   // sKV reread-safe for next tile
    }

    // ======================= Phase 2: masked softmax =======================
    if (tid < S_DIM) {
        float* row = sP + tid * SP_PITCH;
        float m = -3.0e38f;
        for (int t = 0; t < T_DIM; ++t) {
            float v = row[t];
            float l = (v == 0.0f) ? -100000.0f : v;   // mask: p==0 -> p-INF
            row[t] = l;
            m = fmaxf(m, l);
        }
        float sum = 0.0f;
        for (int t = 0; t < T_DIM; ++t) {
            float e = expf(row[t] - m);
            row[t] = e;
            sum += e;
        }
        float inv = 1.0f / sum;
        for (int t = 0; t < T_DIM; ++t) row[t] *= inv;
    }
    __syncthreads();

    // ======================= Phase 3: O = P @ V ============================
    const int d0 = tg * 4;
    float o[8][4];
    #pragma unroll
    for (int j = 0; j < 8; ++j)
        #pragma unroll
        for (int i = 0; i < 4; ++i) o[j][i] = 0.0f;

    for (int tile = 0; tile < N_TILES; ++tile) {
        const int t0 = tile * T_TILE;

        // Load V tile natural layout: values[t0+tt][d] -> sKV[tt][d]
        const float4* v4 = (const float4*)(vbase + (size_t)t0 * D_DIM);
        for (int i = tid; i < T_TILE * (D_DIM / 4); i += THREADS) {
            int tt = i >> 4;
            int c4 = i & 15;
            *(float4*)&sKV[tt * SK_PITCH + c4 * 4] = v4[i];
        }
        __syncthreads();

        #pragma unroll 4
        for (int kt = 0; kt < T_TILE; ++kt) {
            float a[8];
            #pragma unroll
            for (int j = 0; j < 8; ++j)
                a[j] = sP[(s0 + j) * SP_PITCH + t0 + kt];
            float4 b = *(const float4*)&sKV[kt * SK_PITCH + d0];
            float bb[4] = {b.x, b.y, b.z, b.w};
            #pragma unroll
            for (int j = 0; j < 8; ++j)
                #pragma unroll
                for (int i = 0; i < 4; ++i)
                    o[j][i] = fmaf(a[j], bb[i], o[j][i]);
        }
        __syncthreads();
    }

    // ---- Write output ------------------------------------------------------
    float* obase = out + (size_t)bw * S_DIM * D_DIM;
    #pragma unroll
    for (int j = 0; j < 8; ++j) {
        float4 v = make_float4(o[j][0], o[j][1], o[j][2], o[j][3]);
        *(float4*)&obase[(s0 + j) * D_DIM + d0] = v;
    }
}

extern "C" void kernel_launch(void* const* d_in, const int* in_sizes, int n_in,
                              void* d_out, int out_size)
{
    const float* q    = (const float*)d_in[0];
    const float* keys = (const float*)d_in[1];
    const float* vals = (const float*)d_in[2];
    float* out = (float*)d_out;

    const int BW = in_sizes[1] / (T_DIM * D_DIM);   // 2048

    cudaFuncSetAttribute(attention_encoder_kernel,
                         cudaFuncAttributeMaxDynamicSharedMemorySize, SMEM_BYTES);
    attention_encoder_kernel<<<BW, THREADS, SMEM_BYTES>>>(q, keys, vals, out);
}

// round 3
// speedup vs baseline: 1.4988x; 1.4988x over previous
#include <cuda_runtime.h>
#include <cuda_bf16.h>
#include <cstdint>

// B*W = 2048 independent problems.
//   query  [S=128, D=64]  fp32 (shared)   keys/values [BW, T=256, D=64] fp32
//   out    [BW, S=128, D=64] fp32
#define S_DIM 128
#define D_DIM 64
#define T_DIM 256
#define THREADS 256

// ---------------- smem layout (bytes) ----------------
#define SM_STAT 0                       // pmax[256] @0, psum[256] @1024
#define SM_P    2048                    // fp32 [128][256], col index XORed with (row&31)
#define SM_A    (SM_P + 131072)         // Qhi(16K) Qlo(16K) -> later Phi/Plo slice [128][64] bf16
#define SM_B    (SM_A + 32768)          // Khi(32K) Klo(32K) -> later Vhi/Vlo [256][64] bf16
#define SMEM_BYTES (SM_B + 65536)       // 231424

__device__ __forceinline__ uint32_t smem_u32(const void* p) {
    uint32_t a;
    asm("{ .reg .u64 t; cvta.to.shared.u64 t, %1; cvt.u32.u64 %0, t; }" : "=r"(a) : "l"(p));
    return a;
}
__device__ __forceinline__ uint32_t swz(uint32_t b) { return b ^ ((b >> 3) & 0x70); }
__device__ __forceinline__ int pidx(int r, int c) { return r * 256 + (c ^ (r & 31)); }

// fp32 -> (hi bf16, lo bf16)
__device__ __forceinline__ void split2(float x, uint16_t& h, uint16_t& l) {
    __nv_bfloat16 bh = __float2bfloat16_rn(x);
    float r = x - __bfloat162float(bh);
    __nv_bfloat16 bl = __float2bfloat16_rn(r);
    h = __bfloat16_as_ushort(bh);
    l = __bfloat16_as_ushort(bl);
}

#define LDSM_X4(R0,R1,R2,R3,A) \
    asm volatile("ldmatrix.sync.aligned.m8n8.x4.shared.b16 {%0,%1,%2,%3}, [%4];" \
        : "=r"(R0),"=r"(R1),"=r"(R2),"=r"(R3) : "r"(A))
#define LDSM_X4T(R0,R1,R2,R3,A) \
    asm volatile("ldmatrix.sync.aligned.m8n8.x4.trans.shared.b16 {%0,%1,%2,%3}, [%4];" \
        : "=r"(R0),"=r"(R1),"=r"(R2),"=r"(R3) : "r"(A))

__device__ __forceinline__ void mma16816(float c[4], const uint32_t a[4], const uint32_t b[2]) {
    asm volatile("mma.sync.aligned.m16n8k16.row.col.f32.bf16.bf16.f32 "
        "{%0,%1,%2,%3}, {%4,%5,%6,%7}, {%8,%9}, {%0,%1,%2,%3};"
        : "+f"(c[0]), "+f"(c[1]), "+f"(c[2]), "+f"(c[3])
        : "r"(a[0]), "r"(a[1]), "r"(a[2]), "r"(a[3]), "r"(b[0]), "r"(b[1]));
}

__global__ void __launch_bounds__(THREADS, 1)
attn_mma_kernel(const float* __restrict__ q,
                const float* __restrict__ keys,
                const float* __restrict__ values,
                float* __restrict__ out)
{
    extern __shared__ char smem[];
    const uint32_t sb = smem_u32(smem);
    float* sPf  = (float*)(smem + SM_P);
    float* pmax = (float*)(smem + SM_STAT);
    float* psum = (float*)(smem + SM_STAT + 1024);

    const int tid = threadIdx.x;
    const int w   = tid >> 5;
    const int l   = tid & 31;
    const int bw  = blockIdx.x;

    const float4* q4 = (const float4*)q;
    const float4* k4 = (const float4*)(keys   + (size_t)bw * T_DIM * D_DIM);
    const float4* v4 = (const float4*)(values + (size_t)bw * T_DIM * D_DIM);

    // ================= Phase 0: Q,K -> bf16 hi/lo SW128 tiles =================
    #pragma unroll 2
    for (int i = tid; i < S_DIM * (D_DIM / 4); i += THREADS) {
        int s = i >> 4, d4 = i & 15;
        float4 v = q4[i];
        float f[4] = {v.x, v.y, v.z, v.w};
        uint16_t hh[4], ll[4];
        #pragma unroll
        for (int j = 0; j < 4; ++j) split2(f[j], hh[j], ll[j]);
        uint32_t off = swz((uint32_t)(s * 128 + d4 * 8));
        *(uint2*)(smem + SM_A + off)         = make_uint2((uint32_t)hh[0] | ((uint32_t)hh[1] << 16),
                                                          (uint32_t)hh[2] | ((uint32_t)hh[3] << 16));
        *(uint2*)(smem + SM_A + 16384 + off) = make_uint2((uint32_t)ll[0] | ((uint32_t)ll[1] << 16),
                                                          (uint32_t)ll[2] | ((uint32_t)ll[3] << 16));
    }
    #pragma unroll 2
    for (int i = tid; i < T_DIM * (D_DIM / 4); i += THREADS) {
        int t = i >> 4, d4 = i & 15;
        float4 v = k4[i];
        float f[4] = {v.x, v.y, v.z, v.w};
        uint16_t hh[4], ll[4];
        #pragma unroll
        for (int j = 0; j < 4; ++j) split2(f[j], hh[j], ll[j]);
        uint32_t off = swz((uint32_t)(t * 128 + d4 * 8));
        *(uint2*)(smem + SM_B + off)         = make_uint2((uint32_t)hh[0] | ((uint32_t)hh[1] << 16),
                                                          (uint32_t)hh[2] | ((uint32_t)hh[3] << 16));
        *(uint2*)(smem + SM_B + 32768 + off) = make_uint2((uint32_t)ll[0] | ((uint32_t)ll[1] << 16),
                                                          (uint32_t)ll[2] | ((uint32_t)ll[3] << 16));
    }
    __syncthreads();

    // ================= Phase 1: logits = Q @ K^T (split-3 bf16 mma) ===========
    {
        const int m0 = (w & 1) * 64;
        const int n0 = (w >> 1) * 64;
        const uint32_t qhB = sb + SM_A, qlB = sb + SM_A + 16384;
        const uint32_t khB = sb + SM_B, klB = sb + SM_B + 32768;
        const int a_row = l & 15, a_kh = l >> 4;           // A lane pattern
        const int b_i = l >> 3, b_row = l & 7;             // B lane pattern
        const int b_nh = (b_i >> 1) * 8, b_kh = (b_i & 1) * 16;

        #pragma unroll
        for (int nc = 0; nc < 2; ++nc) {
            const int n = n0 + nc * 32;
            float acc[4][4][4];
            #pragma unroll
            for (int mt = 0; mt < 4; ++mt)
                #pragma unroll
                for (int nt = 0; nt < 4; ++nt)
                    #pragma unroll
                    for (int e = 0; e < 4; ++e) acc[mt][nt][e] = 0.0f;

            #pragma unroll
            for (int k16 = 0; k16 < 4; ++k16) {
                uint32_t Ahi[4][4], Alo[4][4], Bhi[4][2], Blo[4][2];
                #pragma unroll
                for (int mt = 0; mt < 4; ++mt) {
                    uint32_t off = swz((uint32_t)((m0 + mt * 16 + a_row) * 128 + k16 * 32 + a_kh * 16));
                    LDSM_X4(Ahi[mt][0], Ahi[mt][1], Ahi[mt][2], Ahi[mt][3], qhB + off);
                    LDSM_X4(Alo[mt][0], Alo[mt][1], Alo[mt][2], Alo[mt][3], qlB + off);
                }
                #pragma unroll
                for (int ntp = 0; ntp < 2; ++ntp) {
                    uint32_t off = swz((uint32_t)((n + ntp * 16 + b_nh + b_row) * 128 + k16 * 32 + b_kh));
                    LDSM_X4(Bhi[2*ntp][0], Bhi[2*ntp][1], Bhi[2*ntp+1][0], Bhi[2*ntp+1][1], khB + off);
                    LDSM_X4(Blo[2*ntp][0], Blo[2*ntp][1], Blo[2*ntp+1][0], Blo[2*ntp+1][1], klB + off);
                }
                #pragma unroll
                for (int mt = 0; mt < 4; ++mt)
                    #pragma unroll
                    for (int nt = 0; nt < 4; ++nt) {
                        mma16816(acc[mt][nt], Ahi[mt], Bhi[nt]);
                        mma16816(acc[mt][nt], Ahi[mt], Blo[nt]);
                        mma16816(acc[mt][nt], Alo[mt], Bhi[nt]);
                    }
            }
            // epilogue: scatter to sP (fp32, XOR-swizzled columns)
            const int er = l >> 2, ec = (l & 3) * 2;
            #pragma unroll
            for (int mt = 0; mt < 4; ++mt)
                #pragma unroll
                for (int nt = 0; nt < 4; ++nt) {
                    int r1 = m0 + mt * 16 + er, r2 = r1 + 8;
                    int c  = n + nt * 8 + ec;
                    sPf[pidx(r1, c)]     = acc[mt][nt][0];
                    sPf[pidx(r1, c + 1)] = acc[mt][nt][1];
                    sPf[pidx(r2, c)]     = acc[mt][nt][2];
                    sPf[pidx(r2, c + 1)] = acc[mt][nt][3];
                }
        }
    }
    __syncthreads();

    // ================= Phase 2a: V -> bf16 hi/lo (overwrites K region) ========
    #pragma unroll 2
    for (int i = tid; i < T_DIM * (D_DIM / 4); i += THREADS) {
        int t = i >> 4, d4 = i & 15;
        float4 v = v4[i];
        float f[4] = {v.x, v.y, v.z, v.w};
        uint16_t hh[4], ll[4];
        #pragma unroll
        for (int j = 0; j < 4; ++j) split2(f[j], hh[j], ll[j]);
        uint32_t off = swz((uint32_t)(t * 128 + d4 * 8));
        *(uint2*)(smem + SM_B + off)         = make_uint2((uint32_t)hh[0] | ((uint32_t)hh[1] << 16),
                                                          (uint32_t)hh[2] | ((uint32_t)hh[3] << 16));
        *(uint2*)(smem + SM_B + 32768 + off) = make_uint2((uint32_t)ll[0] | ((uint32_t)ll[1] << 16),
                                                          (uint32_t)ll[2] | ((uint32_t)ll[3] << 16));
    }

    // ================= Phase 2b: masked softmax (deferred normalization) ======
    {
        const int row = tid >> 1, half = tid & 1;
        const int t0 = half * 128;
        float m = -3.0e38f;
        for (int t = t0; t < t0 + 128; ++t) {
            float v = sPf[pidx(row, t)];
            float lg = (v == 0.0f) ? -100000.0f : v;
            m = fmaxf(m, lg);
        }
        pmax[tid] = m;
        __syncthreads();
        float mm = fmaxf(m, pmax[tid ^ 1]);
        float sum = 0.0f;
        for (int t = t0; t < t0 + 128; ++t) {
            float v = sPf[pidx(row, t)];
            float lg = (v == 0.0f) ? -100000.0f : v;
            float e = __expf(lg - mm);
            sPf[pidx(row, t)] = e;
            sum += e;
        }
        psum[tid] = sum;
    }
    __syncthreads();

    // ================= Phase 3: O = P @ V (4 k-slices of 64) ==================
    const int s0 = w * 16;
    float acc2[8][4];
    #pragma unroll
    for (int nt = 0; nt < 8; ++nt)
        #pragma unroll
        for (int e = 0; e < 4; ++e) acc2[nt][e] = 0.0f;

    {
        const uint32_t phB = sb + SM_A, plB = sb + SM_A + 16384;
        const uint32_t vhB = sb + SM_B, vlB = sb + SM_B + 32768;
        const int a_row = l & 15, a_kh = l >> 4;
        const int b_i = l >> 3;
        const int b_toff = (b_i & 1) * 8 + (l & 7);
        const int b_ch = (b_i >> 1) * 16;

        for (int slice = 0; slice < 4; ++slice) {
            // convert P slice -> Phi/Plo bf16 [128][64] (reuses Q region)
            for (int i = tid; i < 4096; i += THREADS) {
                int s = i >> 5, ttp = i & 31;
                int c0 = slice * 64 + 2 * ttp;
                float f0 = sPf[pidx(s, c0)];
                float f1 = sPf[pidx(s, c0 + 1)];
                uint16_t h0, l0, h1, l1;
                split2(f0, h0, l0);
                split2(f1, h1, l1);
                uint32_t off = swz((uint32_t)(s * 128 + ttp * 4));
                *(uint32_t*)(smem + SM_A + off)         = (uint32_t)h0 | ((uint32_t)h1 << 16);
                *(uint32_t*)(smem + SM_A + 16384 + off) = (uint32_t)l0 | ((uint32_t)l1 << 16);
            }
            __syncthreads();

            #pragma unroll
            for (int k16 = 0; k16 < 4; ++k16) {
                uint32_t Ah[4], Al[4], Bh[8][2], Bl[8][2];
                {
                    uint32_t off = swz((uint32_t)((s0 + a_row) * 128 + k16 * 32 + a_kh * 16));
                    LDSM_X4(Ah[0], Ah[1], Ah[2], Ah[3], phB + off);
                    LDSM_X4(Al[0], Al[1], Al[2], Al[3], plB + off);
                }
                #pragma unroll
                for (int ntp = 0; ntp < 4; ++ntp) {
                    int t = slice * 64 + k16 * 16 + b_toff;
                    uint32_t off = swz((uint32_t)(t * 128 + ntp * 32 + b_ch));
                    LDSM_X4T(Bh[2*ntp][0], Bh[2*ntp][1], Bh[2*ntp+1][0], Bh[2*ntp+1][1], vhB + off);
                    LDSM_X4T(Bl[2*ntp][0], Bl[2*ntp][1], Bl[2*ntp+1][0], Bl[2*ntp+1][1], vlB + off);
                }
                #pragma unroll
                for (int nt = 0; nt < 8; ++nt) {
                    mma16816(acc2[nt], Ah, Bh[nt]);
                    mma16816(acc2[nt], Ah, Bl[nt]);
                    mma16816(acc2[nt], Al, Bh[nt]);
                }
            }
            __syncthreads();   // A region reused next slice
        }
    }

    // ================= Epilogue: scale by 1/rowsum, write out ================
    {
        const int er = l >> 2, ec = (l & 3) * 2;
        const int r1 = s0 + er, r2 = r1 + 8;
        float inv1 = 1.0f / (psum[2 * r1] + psum[2 * r1 + 1]);
        float inv2 = 1.0f / (psum[2 * r2] + psum[2 * r2 + 1]);
        float* ob = out + (size_t)bw * (S_DIM * D_DIM);
        #pragma unroll
        for (int nt = 0; nt < 8; ++nt) {
            int c = nt * 8 + ec;
            *(float2*)(ob + r1 * 64 + c) = make_float2(acc2[nt][0] * inv1, acc2[nt][1] * inv1);
            *(float2*)(ob + r2 * 64 + c) = make_float2(acc2[nt][2] * inv2, acc2[nt][3] * inv2);
        }
    }
}

extern "C" void kernel_launch(void* const* d_in, const int* in_sizes, int n_in,
                              void* d_out, int out_size)
{
    const float* q    = (const float*)d_in[0];
    const float* keys = (const float*)d_in[1];
    const float* vals = (const float*)d_in[2];
    float* out = (float*)d_out;

    const int BW = in_sizes[1] / (T_DIM * D_DIM);   // 2048

    cudaFuncSetAttribute(attn_mma_kernel,
                         cudaFuncAttributeMaxDynamicSharedMemorySize, SMEM_BYTES);
    attn_mma_kernel<<<BW, THREADS, SMEM_BYTES>>>(q, keys, vals, out);
}

// round 4
// speedup vs baseline: 2.9997x; 2.0014x over previous
#include <cuda_runtime.h>
#include <cuda_bf16.h>
#include <cstdint>

// B*W = 2048 independent problems.
//   query  [S=128, D=64]  fp32 (shared)   keys/values [BW, T=256, D=64] fp32
//   out    [BW, S=128, D=64] fp32
#define S_DIM 128
#define D_DIM 64
#define T_DIM 256
#define CHUNK 64
#define NCHUNK (T_DIM / CHUNK)
#define THREADS 256

// smem: K chunk hi/lo + V chunk hi/lo, bf16 [64][64], 128B rows, SW128
#define SM_KH 0
#define SM_KL 8192
#define SM_VH 16384
#define SM_VL 24576
#define SMEM_BYTES 32768

__device__ __forceinline__ uint32_t smem_u32(const void* p) {
    uint32_t a;
    asm("{ .reg .u64 t; cvta.to.shared.u64 t, %1; cvt.u32.u64 %0, t; }" : "=r"(a) : "l"(p));
    return a;
}
__device__ __forceinline__ uint32_t swz(uint32_t b) { return b ^ ((b >> 3) & 0x70); }

__device__ __forceinline__ void split2(float x, uint16_t& h, uint16_t& l) {
    __nv_bfloat16 bh = __float2bfloat16_rn(x);
    float r = x - __bfloat162float(bh);
    __nv_bfloat16 bl = __float2bfloat16_rn(r);
    h = __bfloat16_as_ushort(bh);
    l = __bfloat16_as_ushort(bl);
}
__device__ __forceinline__ uint32_t pack2(float a, float b) {
    __nv_bfloat162 p = __floats2bfloat162_rn(a, b);
    return *(uint32_t*)&p;
}
// split a float pair into packed hi and packed lo bf16x2
__device__ __forceinline__ void splitpack(float a, float b, uint32_t& hp, uint32_t& lp) {
    uint16_t ha, la, hb, lb;
    split2(a, ha, la);
    split2(b, hb, lb);
    hp = (uint32_t)ha | ((uint32_t)hb << 16);
    lp = (uint32_t)la | ((uint32_t)lb << 16);
}

#define LDSM_X4(R0,R1,R2,R3,A) \
    asm volatile("ldmatrix.sync.aligned.m8n8.x4.shared.b16 {%0,%1,%2,%3}, [%4];" \
        : "=r"(R0),"=r"(R1),"=r"(R2),"=r"(R3) : "r"(A))
#define LDSM_X4T(R0,R1,R2,R3,A) \
    asm volatile("ldmatrix.sync.aligned.m8n8.x4.trans.shared.b16 {%0,%1,%2,%3}, [%4];" \
        : "=r"(R0),"=r"(R1),"=r"(R2),"=r"(R3) : "r"(A))

__device__ __forceinline__ void mma16816(float c[4], const uint32_t a[4], const uint32_t b[2]) {
    asm volatile("mma.sync.aligned.m16n8k16.row.col.f32.bf16.bf16.f32 "
        "{%0,%1,%2,%3}, {%4,%5,%6,%7}, {%8,%9}, {%0,%1,%2,%3};"
        : "+f"(c[0]), "+f"(c[1]), "+f"(c[2]), "+f"(c[3])
        : "r"(a[0]), "r"(a[1]), "r"(a[2]), "r"(a[3]), "r"(b[0]), "r"(b[1]));
}

__global__ void __launch_bounds__(THREADS)
attn_flash_kernel(const float* __restrict__ q,
                  const float* __restrict__ keys,
                  const float* __restrict__ values,
                  float* __restrict__ out)
{
    extern __shared__ char smem[];
    const uint32_t sb = smem_u32(smem);
    const int tid = threadIdx.x;
    const int w   = tid >> 5;
    const int l   = tid & 31;
    const int bw  = blockIdx.x;
    const int s0  = w * 16;                 // this warp's 16 S-rows

    const float4* k4 = (const float4*)(keys   + (size_t)bw * T_DIM * D_DIM);
    const float4* v4 = (const float4*)(values + (size_t)bw * T_DIM * D_DIM);

    // ---- Q fragments in registers (hi/lo), A-layout m16k16 x 4 k-chunks ----
    uint32_t Qh[4][4], Ql[4][4];
    {
        const int r0 = s0 + (l >> 2);
        const int c0 = (l & 3) * 2;
        #pragma unroll
        for (int kc = 0; kc < 4; ++kc) {
            const float* qb = q + kc * 16 + c0;
            float2 v00 = *(const float2*)(qb + r0 * 64);
            float2 v10 = *(const float2*)(qb + (r0 + 8) * 64);
            float2 v01 = *(const float2*)(qb + r0 * 64 + 8);
            float2 v11 = *(const float2*)(qb + (r0 + 8) * 64 + 8);
            splitpack(v00.x, v00.y, Qh[kc][0], Ql[kc][0]);
            splitpack(v10.x, v10.y, Qh[kc][1], Ql[kc][1]);
            splitpack(v01.x, v01.y, Qh[kc][2], Ql[kc][2]);
            splitpack(v11.x, v11.y, Qh[kc][3], Ql[kc][3]);
        }
    }

    // ldmatrix lane patterns
    const int b_i   = l >> 3;
    const int b_row = l & 7;
    const int b_nh  = (b_i >> 1) * 8;
    const int b_kh  = (b_i & 1) * 16;
    const int b_toff = (b_i & 1) * 8 + (l & 7);
    const int b_ch   = (b_i >> 1) * 16;

    float Oacc[8][4];
    #pragma unroll
    for (int nt = 0; nt < 8; ++nt)
        #pragma unroll
        for (int e = 0; e < 4; ++e) Oacc[nt][e] = 0.0f;
    float rs1 = 0.0f, rs2 = 0.0f;          // unnormalized row sums (2 rows/thread)

    for (int chunk = 0; chunk < NCHUNK; ++chunk) {
        if (chunk) __syncthreads();

        // ---- load + convert K,V chunk -> bf16 hi/lo SW128 smem ----
        const int t0 = chunk * CHUNK;
        #pragma unroll
        for (int i = tid; i < CHUNK * 16; i += THREADS) {
            int t = i >> 4, d4 = i & 15;
            uint32_t off = swz((uint32_t)(t * 128 + d4 * 8));
            float4 kv = k4[(t0 + t) * 16 + d4];
            uint32_t h0, l0, h1, l1;
            splitpack(kv.x, kv.y, h0, l0);
            splitpack(kv.z, kv.w, h1, l1);
            *(uint2*)(smem + SM_KH + off) = make_uint2(h0, h1);
            *(uint2*)(smem + SM_KL + off) = make_uint2(l0, l1);
            float4 vv = v4[(t0 + t) * 16 + d4];
            splitpack(vv.x, vv.y, h0, l0);
            splitpack(vv.z, vv.w, h1, l1);
            *(uint2*)(smem + SM_VH + off) = make_uint2(h0, h1);
            *(uint2*)(smem + SM_VL + off) = make_uint2(l0, l1);
        }
        __syncthreads();

        // ---- GEMM1: S = Q @ K^T  [16 x 64] per warp, split-3 ----
        float acc[8][4];
        #pragma unroll
        for (int nt = 0; nt < 8; ++nt)
            #pragma unroll
            for (int e = 0; e < 4; ++e) acc[nt][e] = 0.0f;

        #pragma unroll
        for (int k16 = 0; k16 < 4; ++k16) {
            #pragma unroll
            for (int ntp = 0; ntp < 4; ++ntp) {
                uint32_t Bh[2][2], Bl[2][2];
                uint32_t off = swz((uint32_t)((ntp * 16 + b_nh + b_row) * 128 + k16 * 32 + b_kh));
                LDSM_X4(Bh[0][0], Bh[0][1], Bh[1][0], Bh[1][1], sb + SM_KH + off);
                LDSM_X4(Bl[0][0], Bl[0][1], Bl[1][0], Bl[1][1], sb + SM_KL + off);
                #pragma unroll
                for (int j = 0; j < 2; ++j) {
                    int nt = 2 * ntp + j;
                    mma16816(acc[nt], Qh[k16], Bh[j]);
                    mma16816(acc[nt], Qh[k16], Bl[j]);
                    mma16816(acc[nt], Ql[k16], Bh[j]);
                }
            }
        }

        // ---- mask + exp (no max subtraction; normalization deferred) ----
        // pack直接 into GEMM2 A-fragments: tile 2kc -> a0/a1, tile 2kc+1 -> a2/a3
        uint32_t Ph[4][4], Pl[4][4];
        #pragma unroll
        for (int nt = 0; nt < 8; ++nt) {
            float e0, e1, e2, e3;
            {
                float v0 = acc[nt][0], v1 = acc[nt][1], v2 = acc[nt][2], v3 = acc[nt][3];
                e0 = __expf((v0 == 0.0f) ? -100000.0f : v0);
                e1 = __expf((v1 == 0.0f) ? -100000.0f : v1);
                e2 = __expf((v2 == 0.0f) ? -100000.0f : v2);
                e3 = __expf((v3 == 0.0f) ? -100000.0f : v3);
            }
            rs1 += e0 + e1;
            rs2 += e2 + e3;
            int kc = nt >> 1, j = nt & 1;
            splitpack(e0, e1, Ph[kc][2 * j],     Pl[kc][2 * j]);
            splitpack(e2, e3, Ph[kc][2 * j + 1], Pl[kc][2 * j + 1]);
        }

        // ---- GEMM2: O += P @ V  [16 x 64] per warp, split-3, A in regs ----
        #pragma unroll
        for (int k16 = 0; k16 < 4; ++k16) {
            #pragma unroll
            for (int ntp = 0; ntp < 4; ++ntp) {
                uint32_t Vh[2][2], Vl[2][2];
                uint32_t off = swz((uint32_t)((k16 * 16 + b_toff) * 128 + ntp * 32 + b_ch));
                LDSM_X4T(Vh[0][0], Vh[0][1], Vh[1][0], Vh[1][1], sb + SM_VH + off);
                LDSM_X4T(Vl[0][0], Vl[0][1], Vl[1][0], Vl[1][1], sb + SM_VL + off);
                #pragma unroll
                for (int j = 0; j < 2; ++j) {
                    int nt = 2 * ntp + j;
                    mma16816(Oacc[nt], Ph[k16], Vh[j]);
                    mma16816(Oacc[nt], Ph[k16], Vl[j]);
                    mma16816(Oacc[nt], Pl[k16], Vh[j]);
                }
            }
        }
    }

    // ---- epilogue: reduce row sums across quad, normalize, store ----
    rs1 += __shfl_xor_sync(0xFFFFFFFFu, rs1, 1);
    rs1 += __shfl_xor_sync(0xFFFFFFFFu, rs1, 2);
    rs2 += __shfl_xor_sync(0xFFFFFFFFu, rs2, 1);
    rs2 += __shfl_xor_sync(0xFFFFFFFFu, rs2, 2);
    float inv1 = 1.0f / rs1;
    float inv2 = 1.0f / rs2;

    float* ob = out + (size_t)bw * (S_DIM * D_DIM);
    const int r1 = s0 + (l >> 2), r2 = r1 + 8;
    const int ec = (l & 3) * 2;
    #pragma unroll
    for (int nt = 0; nt < 8; ++nt) {
        int c = nt * 8 + ec;
        *(float2*)(ob + r1 * 64 + c) = make_float2(Oacc[nt][0] * inv1, Oacc[nt][1] * inv1);
        *(float2*)(ob + r2 * 64 + c) = make_float2(Oacc[nt][2] * inv2, Oacc[nt][3] * inv2);
    }
}

extern "C" void kernel_launch(void* const* d_in, const int* in_sizes, int n_in,
                              void* d_out, int out_size)
{
    const float* q    = (const float*)d_in[0];
    const float* keys = (const float*)d_in[1];
    const float* vals = (const float*)d_in[2];
    float* out = (float*)d_out;

    const int BW = in_sizes[1] / (T_DIM * D_DIM);   // 2048

    cudaFuncSetAttribute(attn_flash_kernel,
                         cudaFuncAttributeMaxDynamicSharedMemorySize, SMEM_BYTES);
    attn_flash_kernel<<<BW, THREADS, SMEM_BYTES>>>(q, keys, vals, out);
}

// round 5
// speedup vs baseline: 3.1692x; 1.0565x over previous
#include <cuda_runtime.h>
#include <cuda_bf16.h>
#include <cstdint>

// B*W = 2048 independent problems.
//   query  [S=128, D=64]  fp32 (shared)   keys/values [BW, T=256, D=64] fp32
//   out    [BW, S=128, D=64] fp32
#define S_DIM 128
#define D_DIM 64
#define T_DIM 256
#define CHUNK 64
#define NCHUNK (T_DIM / CHUNK)
#define THREADS 256

// smem: bf16 K/V hi-lo tiles (single-buffered) + fp32 staging (double-buffered)
#define SM_KH   0
#define SM_KL   8192
#define SM_VH   16384
#define SM_VL   24576
#define SM_STG  32768                    // 2 x 32KB: [K fp32 16KB][V fp32 16KB]
#define SMEM_BYTES (SM_STG + 2 * 32768)  // 98304

__device__ __forceinline__ uint32_t smem_u32(const void* p) {
    uint32_t a;
    asm("{ .reg .u64 t; cvta.to.shared.u64 t, %1; cvt.u32.u64 %0, t; }" : "=r"(a) : "l"(p));
    return a;
}
__device__ __forceinline__ uint32_t swz(uint32_t b) { return b ^ ((b >> 3) & 0x70); }

#define CP_ASYNC16(SA, GA) \
    asm volatile("cp.async.cg.shared.global [%0], [%1], 16;" :: "r"(SA), "l"(GA) : "memory")
#define CP_COMMIT() asm volatile("cp.async.commit_group;" ::: "memory")
#define CP_WAIT(N)  asm volatile("cp.async.wait_group %0;" :: "n"(N) : "memory")

__device__ __forceinline__ void split2(float x, uint16_t& h, uint16_t& l) {
    __nv_bfloat16 bh = __float2bfloat16_rn(x);
    float r = x - __bfloat162float(bh);
    __nv_bfloat16 bl = __float2bfloat16_rn(r);
    h = __bfloat16_as_ushort(bh);
    l = __bfloat16_as_ushort(bl);
}
__device__ __forceinline__ void splitpack(float a, float b, uint32_t& hp, uint32_t& lp) {
    uint16_t ha, la, hb, lb;
    split2(a, ha, la);
    split2(b, hb, lb);
    hp = (uint32_t)ha | ((uint32_t)hb << 16);
    lp = (uint32_t)la | ((uint32_t)lb << 16);
}

#define LDSM_X4(R0,R1,R2,R3,A) \
    asm volatile("ldmatrix.sync.aligned.m8n8.x4.shared.b16 {%0,%1,%2,%3}, [%4];" \
        : "=r"(R0),"=r"(R1),"=r"(R2),"=r"(R3) : "r"(A))
#define LDSM_X4T(R0,R1,R2,R3,A) \
    asm volatile("ldmatrix.sync.aligned.m8n8.x4.trans.shared.b16 {%0,%1,%2,%3}, [%4];" \
        : "=r"(R0),"=r"(R1),"=r"(R2),"=r"(R3) : "r"(A))

__device__ __forceinline__ void mma16816(float c[4], const uint32_t a[4], const uint32_t b[2]) {
    asm volatile("mma.sync.aligned.m16n8k16.row.col.f32.bf16.bf16.f32 "
        "{%0,%1,%2,%3}, {%4,%5,%6,%7}, {%8,%9}, {%0,%1,%2,%3};"
        : "+f"(c[0]), "+f"(c[1]), "+f"(c[2]), "+f"(c[3])
        : "r"(a[0]), "r"(a[1]), "r"(a[2]), "r"(a[3]), "r"(b[0]), "r"(b[1]));
}

__global__ void __launch_bounds__(THREADS)
attn_flash2_kernel(const float* __restrict__ q,
                   const float* __restrict__ keys,
                   const float* __restrict__ values,
                   float* __restrict__ out)
{
    extern __shared__ char smem[];
    const uint32_t sb = smem_u32(smem);
    const int tid = threadIdx.x;
    const int w   = tid >> 5;
    const int l   = tid & 31;
    const int bw  = blockIdx.x;
    const int s0  = w * 16;

    const char* kg = (const char*)(keys   + (size_t)bw * T_DIM * D_DIM);
    const char* vg = (const char*)(values + (size_t)bw * T_DIM * D_DIM);

    // ---- prefetch chunk 0 into stage 0 (16B cp.async, bypasses RF) ----
    {
        const uint32_t sg = sb + SM_STG;
        #pragma unroll
        for (int j = 0; j < 4; ++j) {
            int off = tid * 16 + j * 4096;
            CP_ASYNC16(sg + off,         kg + off);
            CP_ASYNC16(sg + 16384 + off, vg + off);
        }
        CP_COMMIT();
    }

    // ---- Q fragments in registers (hi/lo), overlaps with cp.async ----
    uint32_t Qh[4][4], Ql[4][4];
    {
        const int r0 = s0 + (l >> 2);
        const int c0 = (l & 3) * 2;
        #pragma unroll
        for (int kc = 0; kc < 4; ++kc) {
            const float* qb = q + kc * 16 + c0;
            float2 v00 = *(const float2*)(qb + r0 * 64);
            float2 v10 = *(const float2*)(qb + (r0 + 8) * 64);
            float2 v01 = *(const float2*)(qb + r0 * 64 + 8);
            float2 v11 = *(const float2*)(qb + (r0 + 8) * 64 + 8);
            splitpack(v00.x, v00.y, Qh[kc][0], Ql[kc][0]);
            splitpack(v10.x, v10.y, Qh[kc][1], Ql[kc][1]);
            splitpack(v01.x, v01.y, Qh[kc][2], Ql[kc][2]);
            splitpack(v11.x, v11.y, Qh[kc][3], Ql[kc][3]);
        }
    }

    // ldmatrix lane patterns
    const int b_i   = l >> 3;
    const int b_row = l & 7;
    const int b_nh  = (b_i >> 1) * 8;
    const int b_kh  = (b_i & 1) * 16;
    const int b_toff = (b_i & 1) * 8 + (l & 7);
    const int b_ch   = (b_i >> 1) * 16;

    float Oacc[8][4];
    #pragma unroll
    for (int nt = 0; nt < 8; ++nt)
        #pragma unroll
        for (int e = 0; e < 4; ++e) Oacc[nt][e] = 0.0f;
    float rs1 = 0.0f, rs2 = 0.0f;

    for (int chunk = 0; chunk < NCHUNK; ++chunk) {
        // prefetch next chunk into other stage
        if (chunk < NCHUNK - 1) {
            const uint32_t sg = sb + SM_STG + ((chunk + 1) & 1) * 32768;
            const int base = (chunk + 1) * 16384;
            #pragma unroll
            for (int j = 0; j < 4; ++j) {
                int off = tid * 16 + j * 4096;
                CP_ASYNC16(sg + off,         kg + base + off);
                CP_ASYNC16(sg + 16384 + off, vg + base + off);
            }
            CP_COMMIT();
            CP_WAIT(1);            // current chunk's group done
        } else {
            CP_WAIT(0);
        }
        __syncthreads();           // staging visible to all; prev GEMM2 done

        // ---- convert staging fp32 -> bf16 hi/lo SW128 tiles ----
        {
            const float4* stg = (const float4*)(smem + SM_STG + (chunk & 1) * 32768);
            #pragma unroll
            for (int i = tid; i < CHUNK * 16; i += THREADS) {
                int t = i >> 4, d4 = i & 15;
                uint32_t off = swz((uint32_t)(t * 128 + d4 * 8));
                float4 kv = stg[i];
                uint32_t h0, l0, h1, l1;
                splitpack(kv.x, kv.y, h0, l0);
                splitpack(kv.z, kv.w, h1, l1);
                *(uint2*)(smem + SM_KH + off) = make_uint2(h0, h1);
                *(uint2*)(smem + SM_KL + off) = make_uint2(l0, l1);
                float4 vv = stg[1024 + i];
                splitpack(vv.x, vv.y, h0, l0);
                splitpack(vv.z, vv.w, h1, l1);
                *(uint2*)(smem + SM_VH + off) = make_uint2(h0, h1);
                *(uint2*)(smem + SM_VL + off) = make_uint2(l0, l1);
            }
        }
        __syncthreads();

        // ---- GEMM1: S = Q @ K^T  [16 x 64] per warp, split-3 ----
        float acc[8][4];
        #pragma unroll
        for (int nt = 0; nt < 8; ++nt)
            #pragma unroll
            for (int e = 0; e < 4; ++e) acc[nt][e] = 0.0f;

        #pragma unroll
        for (int k16 = 0; k16 < 4; ++k16) {
            #pragma unroll
            for (int ntp = 0; ntp < 4; ++ntp) {
                uint32_t Bh[2][2], Bl[2][2];
                uint32_t off = swz((uint32_t)((ntp * 16 + b_nh + b_row) * 128 + k16 * 32 + b_kh));
                LDSM_X4(Bh[0][0], Bh[0][1], Bh[1][0], Bh[1][1], sb + SM_KH + off);
                LDSM_X4(Bl[0][0], Bl[0][1], Bl[1][0], Bl[1][1], sb + SM_KL + off);
                #pragma unroll
                for (int j = 0; j < 2; ++j) {
                    int nt = 2 * ntp + j;
                    mma16816(acc[nt], Qh[k16], Bh[j]);
                    mma16816(acc[nt], Qh[k16], Bl[j]);
                    mma16816(acc[nt], Ql[k16], Bh[j]);
                }
            }
        }

        // ---- mask + exp (no max subtraction; normalization deferred) ----
        uint32_t Ph[4][4], Pl[4][4];
        #pragma unroll
        for (int nt = 0; nt < 8; ++nt) {
            float v0 = acc[nt][0], v1 = acc[nt][1], v2 = acc[nt][2], v3 = acc[nt][3];
            float e0 = __expf((v0 == 0.0f) ? -100000.0f : v0);
            float e1 = __expf((v1 == 0.0f) ? -100000.0f : v1);
            float e2 = __expf((v2 == 0.0f) ? -100000.0f : v2);
            float e3 = __expf((v3 == 0.0f) ? -100000.0f : v3);
            rs1 += e0 + e1;
            rs2 += e2 + e3;
            int kc = nt >> 1, j = nt & 1;
            splitpack(e0, e1, Ph[kc][2 * j],     Pl[kc][2 * j]);
            splitpack(e2, e3, Ph[kc][2 * j + 1], Pl[kc][2 * j + 1]);
        }

        // ---- GEMM2: O += P @ V  [16 x 64] per warp, split-3 ----
        #pragma unroll
        for (int k16 = 0; k16 < 4; ++k16) {
            #pragma unroll
            for (int ntp = 0; ntp < 4; ++ntp) {
                uint32_t Vh[2][2], Vl[2][2];
                uint32_t off = swz((uint32_t)((k16 * 16 + b_toff) * 128 + ntp * 32 + b_ch));
                LDSM_X4T(Vh[0][0], Vh[0][1], Vh[1][0], Vh[1][1], sb + SM_VH + off);
                LDSM_X4T(Vl[0][0], Vl[0][1], Vl[1][0], Vl[1][1], sb + SM_VL + off);
                #pragma unroll
                for (int j = 0; j < 2; ++j) {
                    int nt = 2 * ntp + j;
                    mma16816(Oacc[nt], Ph[k16], Vh[j]);
                    mma16816(Oacc[nt], Ph[k16], Vl[j]);
                    mma16816(Oacc[nt], Pl[k16], Vh[j]);
                }
            }
        }
    }

    // ---- epilogue: reduce row sums across quad, normalize, store ----
    rs1 += __shfl_xor_sync(0xFFFFFFFFu, rs1, 1);
    rs1 += __shfl_xor_sync(0xFFFFFFFFu, rs1, 2);
    rs2 += __shfl_xor_sync(0xFFFFFFFFu, rs2, 1);
    rs2 += __shfl_xor_sync(0xFFFFFFFFu, rs2, 2);
    float inv1 = 1.0f / rs1;
    float inv2 = 1.0f / rs2;

    float* ob = out + (size_t)bw * (S_DIM * D_DIM);
    const int r1 = s0 + (l >> 2), r2 = r1 + 8;
    const int ec = (l & 3) * 2;
    #pragma unroll
    for (int nt = 0; nt < 8; ++nt) {
        int c = nt * 8 + ec;
        *(float2*)(ob + r1 * 64 + c) = make_float2(Oacc[nt][0] * inv1, Oacc[nt][1] * inv1);
        *(float2*)(ob + r2 * 64 + c) = make_float2(Oacc[nt][2] * inv2, Oacc[nt][3] * inv2);
    }
}

extern "C" void kernel_launch(void* const* d_in, const int* in_sizes, int n_in,
                              void* d_out, int out_size)
{
    const float* q    = (const float*)d_in[0];
    const float* keys = (const float*)d_in[1];
    const float* vals = (const float*)d_in[2];
    float* out = (float*)d_out;

    const int BW = in_sizes[1] / (T_DIM * D_DIM);   // 2048

    cudaFuncSetAttribute(attn_flash2_kernel,
                         cudaFuncAttributeMaxDynamicSharedMemorySize, SMEM_BYTES);
    attn_flash2_kernel<<<BW, THREADS, SMEM_BYTES>>>(q, keys, vals, out);
}

// round 6
// speedup vs baseline: 4.1167x; 1.2989x over previous
#include <cuda_runtime.h>
#include <cuda_bf16.h>
#include <cstdint>

// B*W = 2048 independent problems.
//   query  [S=128, D=64]  fp32 (shared)   keys/values [BW, T=256, D=64] fp32
//   out    [BW, S=128, D=64] fp32
#define S_DIM 128
#define D_DIM 64
#define T_DIM 256
#define CHUNK 64
#define NCHUNK (T_DIM / CHUNK)
#define THREADS 256

// smem (bytes): Q hi/lo bf16 [128][64] + K/V hi/lo bf16 [64][64] + fp32 staging
#define SM_QH   0
#define SM_QL   16384
#define SM_KH   32768
#define SM_KL   40960
#define SM_VH   49152
#define SM_VL   57344
#define SM_STG  65536                    // 32KB: K fp32 16KB + V fp32 16KB
#define SMEM_BYTES (SM_STG + 32768)      // 98304 (96KB) -> 2 CTAs/SM

__device__ __forceinline__ uint32_t smem_u32(const void* p) {
    uint32_t a;
    asm("{ .reg .u64 t; cvta.to.shared.u64 t, %1; cvt.u32.u64 %0, t; }" : "=r"(a) : "l"(p));
    return a;
}
__device__ __forceinline__ uint32_t swz(uint32_t b) { return b ^ ((b >> 3) & 0x70); }

#define CP_ASYNC16(SA, GA) \
    asm volatile("cp.async.cg.shared.global [%0], [%1], 16;" :: "r"(SA), "l"(GA) : "memory")
#define CP_COMMIT() asm volatile("cp.async.commit_group;" ::: "memory")
#define CP_WAIT0()  asm volatile("cp.async.wait_group 0;" ::: "memory")

__device__ __forceinline__ void split2(float x, uint16_t& h, uint16_t& l) {
    __nv_bfloat16 bh = __float2bfloat16_rn(x);
    float r = x - __bfloat162float(bh);
    __nv_bfloat16 bl = __float2bfloat16_rn(r);
    h = __bfloat16_as_ushort(bh);
    l = __bfloat16_as_ushort(bl);
}
__device__ __forceinline__ void splitpack(float a, float b, uint32_t& hp, uint32_t& lp) {
    uint16_t ha, la, hb, lb;
    split2(a, ha, la);
    split2(b, hb, lb);
    hp = (uint32_t)ha | ((uint32_t)hb << 16);
    lp = (uint32_t)la | ((uint32_t)lb << 16);
}

#define LDSM_X4(R0,R1,R2,R3,A) \
    asm volatile("ldmatrix.sync.aligned.m8n8.x4.shared.b16 {%0,%1,%2,%3}, [%4];" \
        : "=r"(R0),"=r"(R1),"=r"(R2),"=r"(R3) : "r"(A))
#define LDSM_X4T(R0,R1,R2,R3,A) \
    asm volatile("ldmatrix.sync.aligned.m8n8.x4.trans.shared.b16 {%0,%1,%2,%3}, [%4];" \
        : "=r"(R0),"=r"(R1),"=r"(R2),"=r"(R3) : "r"(A))

__device__ __forceinline__ void mma16816(float c[4], const uint32_t a[4], const uint32_t b[2]) {
    asm volatile("mma.sync.aligned.m16n8k16.row.col.f32.bf16.bf16.f32 "
        "{%0,%1,%2,%3}, {%4,%5,%6,%7}, {%8,%9}, {%0,%1,%2,%3};"
        : "+f"(c[0]), "+f"(c[1]), "+f"(c[2]), "+f"(c[3])
        : "r"(a[0]), "r"(a[1]), "r"(a[2]), "r"(a[3]), "r"(b[0]), "r"(b[1]));
}

__global__ void __launch_bounds__(THREADS, 2)
attn_flash3_kernel(const float* __restrict__ q,
                   const float* __restrict__ keys,
                   const float* __restrict__ values,
                   float* __restrict__ out)
{
    extern __shared__ char smem[];
    const uint32_t sb = smem_u32(smem);
    const int tid = threadIdx.x;
    const int w   = tid >> 5;
    const int l   = tid & 31;
    const int bw  = blockIdx.x;
    const int s0  = w * 16;

    const char* kg = (const char*)(keys   + (size_t)bw * T_DIM * D_DIM);
    const char* vg = (const char*)(values + (size_t)bw * T_DIM * D_DIM);

    // ---- prefetch chunk 0 (16B cp.async, bypasses RF) ----
    {
        const uint32_t sg = sb + SM_STG;
        #pragma unroll
        for (int j = 0; j < 4; ++j) {
            int off = tid * 16 + j * 4096;
            CP_ASYNC16(sg + off,         kg + off);
            CP_ASYNC16(sg + 16384 + off, vg + off);
        }
        CP_COMMIT();
    }

    // ---- convert Q -> smem bf16 hi/lo (overlaps with cp.async) ----
    {
        const float4* q4 = (const float4*)q;
        #pragma unroll
        for (int i = tid; i < S_DIM * 16; i += THREADS) {
            int s = i >> 4, d4 = i & 15;
            uint32_t off = swz((uint32_t)(s * 128 + d4 * 8));
            float4 v = q4[i];
            uint32_t h0, l0, h1, l1;
            splitpack(v.x, v.y, h0, l0);
            splitpack(v.z, v.w, h1, l1);
            *(uint2*)(smem + SM_QH + off) = make_uint2(h0, h1);
            *(uint2*)(smem + SM_QL + off) = make_uint2(l0, l1);
        }
    }

    // ldmatrix lane patterns
    const int a_row  = l & 15;            // A frag
    const int a_kh   = l >> 4;
    const int b_i    = l >> 3;
    const int b_row  = l & 7;
    const int b_nh   = (b_i >> 1) * 8;
    const int b_kh   = (b_i & 1) * 16;
    const int b_toff = (b_i & 1) * 8 + (l & 7);
    const int b_ch   = (b_i >> 1) * 16;

    float Oacc[8][4];
    #pragma unroll
    for (int nt = 0; nt < 8; ++nt)
        #pragma unroll
        for (int e = 0; e < 4; ++e) Oacc[nt][e] = 0.0f;
    float rs1 = 0.0f, rs2 = 0.0f;

    for (int chunk = 0; chunk < NCHUNK; ++chunk) {
        CP_WAIT0();                // staging data arrived
        __syncthreads();           // + all warps done with prev GEMM2 (tiles free)

        // ---- convert staging fp32 -> K/V bf16 hi/lo SW128 tiles ----
        {
            const float4* stg = (const float4*)(smem + SM_STG);
            #pragma unroll
            for (int i = tid; i < CHUNK * 16; i += THREADS) {
                int t = i >> 4, d4 = i & 15;
                uint32_t off = swz((uint32_t)(t * 128 + d4 * 8));
                float4 kv = stg[i];
                uint32_t h0, l0, h1, l1;
                splitpack(kv.x, kv.y, h0, l0);
                splitpack(kv.z, kv.w, h1, l1);
                *(uint2*)(smem + SM_KH + off) = make_uint2(h0, h1);
                *(uint2*)(smem + SM_KL + off) = make_uint2(l0, l1);
                float4 vv = stg[1024 + i];
                splitpack(vv.x, vv.y, h0, l0);
                splitpack(vv.z, vv.w, h1, l1);
                *(uint2*)(smem + SM_VH + off) = make_uint2(h0, h1);
                *(uint2*)(smem + SM_VL + off) = make_uint2(l0, l1);
            }
        }
        __syncthreads();           // tiles visible; staging reads complete

        // ---- prefetch next chunk (overlaps both GEMMs) ----
        if (chunk < NCHUNK - 1) {
            const uint32_t sg = sb + SM_STG;
            const int base = (chunk + 1) * 16384;
            #pragma unroll
            for (int j = 0; j < 4; ++j) {
                int off = tid * 16 + j * 4096;
                CP_ASYNC16(sg + off,         kg + base + off);
                CP_ASYNC16(sg + 16384 + off, vg + base + off);
            }
            CP_COMMIT();
        }

        // ---- GEMM1: S = Q @ K^T  [16 x 64] per warp, split-3 ----
        float acc[8][4];
        #pragma unroll
        for (int nt = 0; nt < 8; ++nt)
            #pragma unroll
            for (int e = 0; e < 4; ++e) acc[nt][e] = 0.0f;

        #pragma unroll
        for (int k16 = 0; k16 < 4; ++k16) {
            uint32_t Ah[4], Al[4];
            {
                uint32_t off = swz((uint32_t)((s0 + a_row) * 128 + k16 * 32 + a_kh * 16));
                LDSM_X4(Ah[0], Ah[1], Ah[2], Ah[3], sb + SM_QH + off);
                LDSM_X4(Al[0], Al[1], Al[2], Al[3], sb + SM_QL + off);
            }
            #pragma unroll
            for (int ntp = 0; ntp < 4; ++ntp) {
                uint32_t Bh[2][2], Bl[2][2];
                uint32_t off = swz((uint32_t)((ntp * 16 + b_nh + b_row) * 128 + k16 * 32 + b_kh));
                LDSM_X4(Bh[0][0], Bh[0][1], Bh[1][0], Bh[1][1], sb + SM_KH + off);
                LDSM_X4(Bl[0][0], Bl[0][1], Bl[1][0], Bl[1][1], sb + SM_KL + off);
                #pragma unroll
                for (int j = 0; j < 2; ++j) {
                    int nt = 2 * ntp + j;
                    mma16816(acc[nt], Ah, Bh[j]);
                    mma16816(acc[nt], Ah, Bl[j]);
                    mma16816(acc[nt], Al, Bh[j]);
                }
            }
        }

        // ---- mask + exp (no max subtraction; normalization deferred) ----
        uint32_t Ph[4][4], Pl[4][4];
        #pragma unroll
        for (int nt = 0; nt < 8; ++nt) {
            float v0 = acc[nt][0], v1 = acc[nt][1], v2 = acc[nt][2], v3 = acc[nt][3];
            float e0 = __expf((v0 == 0.0f) ? -100000.0f : v0);
            float e1 = __expf((v1 == 0.0f) ? -100000.0f : v1);
            float e2 = __expf((v2 == 0.0f) ? -100000.0f : v2);
            float e3 = __expf((v3 == 0.0f) ? -100000.0f : v3);
            rs1 += e0 + e1;
            rs2 += e2 + e3;
            int kc = nt >> 1, j = nt & 1;
            splitpack(e0, e1, Ph[kc][2 * j],     Pl[kc][2 * j]);
            splitpack(e2, e3, Ph[kc][2 * j + 1], Pl[kc][2 * j + 1]);
        }

        // ---- GEMM2: O += P @ V  [16 x 64] per warp, split-3 ----
        #pragma unroll
        for (int k16 = 0; k16 < 4; ++k16) {
            #pragma unroll
            for (int ntp = 0; ntp < 4; ++ntp) {
                uint32_t Vh[2][2], Vl[2][2];
                uint32_t off = swz((uint32_t)((k16 * 16 + b_toff) * 128 + ntp * 32 + b_ch));
                LDSM_X4T(Vh[0][0], Vh[0][1], Vh[1][0], Vh[1][1], sb + SM_VH + off);
                LDSM_X4T(Vl[0][0], Vl[0][1], Vl[1][0], Vl[1][1], sb + SM_VL + off);
                #pragma unroll
                for (int j = 0; j < 2; ++j) {
                    int nt = 2 * ntp + j;
                    mma16816(Oacc[nt], Ph[k16], Vh[j]);
                    mma16816(Oacc[nt], Ph[k16], Vl[j]);
                    mma16816(Oacc[nt], Pl[k16], Vh[j]);
                }
            }
        }
    }

    // ---- epilogue: reduce row sums across quad, normalize, store ----
    rs1 += __shfl_xor_sync(0xFFFFFFFFu, rs1, 1);
    rs1 += __shfl_xor_sync(0xFFFFFFFFu, rs1, 2);
    rs2 += __shfl_xor_sync(0xFFFFFFFFu, rs2, 1);
    rs2 += __shfl_xor_sync(0xFFFFFFFFu, rs2, 2);
    float inv1 = 1.0f / rs1;
    float inv2 = 1.0f / rs2;

    float* ob = out + (size_t)bw * (S_DIM * D_DIM);
    const int r1 = s0 + (l >> 2), r2 = r1 + 8;
    const int ec = (l & 3) * 2;
    #pragma unroll
    for (int nt = 0; nt < 8; ++nt) {
        int c = nt * 8 + ec;
        *(float2*)(ob + r1 * 64 + c) = make_float2(Oacc[nt][0] * inv1, Oacc[nt][1] * inv1);
        *(float2*)(ob + r2 * 64 + c) = make_float2(Oacc[nt][2] * inv2, Oacc[nt][3] * inv2);
    }
}

extern "C" void kernel_launch(void* const* d_in, const int* in_sizes, int n_in,
                              void* d_out, int out_size)
{
    const float* q    = (const float*)d_in[0];
    const float* keys = (const float*)d_in[1];
    const float* vals = (const float*)d_in[2];
    float* out = (float*)d_out;

    const int BW = in_sizes[1] / (T_DIM * D_DIM);   // 2048

    cudaFuncSetAttribute(attn_flash3_kernel,
                         cudaFuncAttributeMaxDynamicSharedMemorySize, SMEM_BYTES);
    attn_flash3_kernel<<<BW, THREADS, SMEM_BYTES>>>(q, keys, vals, out);
}

// round 7
// speedup vs baseline: 5.4503x; 1.3240x over previous
#include <cuda_runtime.h>
#include <cuda_bf16.h>
#include <cuda_fp16.h>
#include <cstdint>

// B*W = 2048 independent problems.
//   query  [S=128, D=64]  fp32 (shared)   keys/values [BW, T=256, D=64] fp32
//   out    [BW, S=128, D=64] fp32
#define S_DIM 128
#define D_DIM 64
#define T_DIM 256
#define CHUNK 64
#define NCHUNK (T_DIM / CHUNK)
#define THREADS 256

// smem (bytes): Q hi/lo bf16 + K hi/lo bf16 + V fp16 + fp32 staging
#define SM_QH   0                        // [128][64] bf16 = 16KB
#define SM_QL   16384
#define SM_KH   32768                    // [64][64] bf16 = 8KB
#define SM_KL   40960
#define SM_VF   49152                    // [64][64] fp16 = 8KB
#define SM_STG  57344                    // 32KB: K fp32 16KB + V fp32 16KB
#define SMEM_BYTES (SM_STG + 32768)      // 90112 (88KB) -> 2 CTAs/SM

__device__ __forceinline__ uint32_t smem_u32(const void* p) {
    uint32_t a;
    asm("{ .reg .u64 t; cvta.to.shared.u64 t, %1; cvt.u32.u64 %0, t; }" : "=r"(a) : "l"(p));
    return a;
}
__device__ __forceinline__ uint32_t swz(uint32_t b) { return b ^ ((b >> 3) & 0x70); }

#define CP_ASYNC16(SA, GA) \
    asm volatile("cp.async.cg.shared.global [%0], [%1], 16;" :: "r"(SA), "l"(GA) : "memory")
#define CP_COMMIT() asm volatile("cp.async.commit_group;" ::: "memory")
#define CP_WAIT0()  asm volatile("cp.async.wait_group 0;" ::: "memory")

__device__ __forceinline__ void split2(float x, uint16_t& h, uint16_t& l) {
    __nv_bfloat16 bh = __float2bfloat16_rn(x);
    float r = x - __bfloat162float(bh);
    __nv_bfloat16 bl = __float2bfloat16_rn(r);
    h = __bfloat16_as_ushort(bh);
    l = __bfloat16_as_ushort(bl);
}
__device__ __forceinline__ void splitpack(float a, float b, uint32_t& hp, uint32_t& lp) {
    uint16_t ha, la, hb, lb;
    split2(a, ha, la);
    split2(b, hb, lb);
    hp = (uint32_t)ha | ((uint32_t)hb << 16);
    lp = (uint32_t)la | ((uint32_t)lb << 16);
}
__device__ __forceinline__ uint32_t packh2(float a, float b) {
    __half2 p = __floats2half2_rn(a, b);
    return *(uint32_t*)&p;
}

#define LDSM_X4(R0,R1,R2,R3,A) \
    asm volatile("ldmatrix.sync.aligned.m8n8.x4.shared.b16 {%0,%1,%2,%3}, [%4];" \
        : "=r"(R0),"=r"(R1),"=r"(R2),"=r"(R3) : "r"(A))
#define LDSM_X4T(R0,R1,R2,R3,A) \
    asm volatile("ldmatrix.sync.aligned.m8n8.x4.trans.shared.b16 {%0,%1,%2,%3}, [%4];" \
        : "=r"(R0),"=r"(R1),"=r"(R2),"=r"(R3) : "r"(A))

__device__ __forceinline__ void mma_bf16(float c[4], const uint32_t a[4], const uint32_t b[2]) {
    asm volatile("mma.sync.aligned.m16n8k16.row.col.f32.bf16.bf16.f32 "
        "{%0,%1,%2,%3}, {%4,%5,%6,%7}, {%8,%9}, {%0,%1,%2,%3};"
        : "+f"(c[0]), "+f"(c[1]), "+f"(c[2]), "+f"(c[3])
        : "r"(a[0]), "r"(a[1]), "r"(a[2]), "r"(a[3]), "r"(b[0]), "r"(b[1]));
}
__device__ __forceinline__ void mma_f16(float c[4], const uint32_t a[4], const uint32_t b[2]) {
    asm volatile("mma.sync.aligned.m16n8k16.row.col.f32.f16.f16.f32 "
        "{%0,%1,%2,%3}, {%4,%5,%6,%7}, {%8,%9}, {%0,%1,%2,%3};"
        : "+f"(c[0]), "+f"(c[1]), "+f"(c[2]), "+f"(c[3])
        : "r"(a[0]), "r"(a[1]), "r"(a[2]), "r"(a[3]), "r"(b[0]), "r"(b[1]));
}

__global__ void __launch_bounds__(THREADS, 2)
attn_flash4_kernel(const float* __restrict__ q,
                   const float* __restrict__ keys,
                   const float* __restrict__ values,
                   float* __restrict__ out)
{
    extern __shared__ char smem[];
    const uint32_t sb = smem_u32(smem);
    const int tid = threadIdx.x;
    const int w   = tid >> 5;
    const int l   = tid & 31;
    const int bw  = blockIdx.x;
    const int s0  = w * 16;

    const char* kg = (const char*)(keys   + (size_t)bw * T_DIM * D_DIM);
    const char* vg = (const char*)(values + (size_t)bw * T_DIM * D_DIM);

    // ---- prefetch chunk 0 (16B cp.async, bypasses RF) ----
    {
        const uint32_t sg = sb + SM_STG;
        #pragma unroll
        for (int j = 0; j < 4; ++j) {
            int off = tid * 16 + j * 4096;
            CP_ASYNC16(sg + off,         kg + off);
            CP_ASYNC16(sg + 16384 + off, vg + off);
        }
        CP_COMMIT();
    }

    // ---- convert Q -> smem bf16 hi/lo (overlaps with cp.async) ----
    {
        const float4* q4 = (const float4*)q;
        #pragma unroll
        for (int i = tid; i < S_DIM * 16; i += THREADS) {
            int s = i >> 4, d4 = i & 15;
            uint32_t off = swz((uint32_t)(s * 128 + d4 * 8));
            float4 v = q4[i];
            uint32_t h0, l0, h1, l1;
            splitpack(v.x, v.y, h0, l0);
            splitpack(v.z, v.w, h1, l1);
            *(uint2*)(smem + SM_QH + off) = make_uint2(h0, h1);
            *(uint2*)(smem + SM_QL + off) = make_uint2(l0, l1);
        }
    }

    // ldmatrix lane patterns
    const int a_row  = l & 15;
    const int a_kh   = l >> 4;
    const int b_i    = l >> 3;
    const int b_row  = l & 7;
    const int b_nh   = (b_i >> 1) * 8;
    const int b_kh   = (b_i & 1) * 16;
    const int b_toff = (b_i & 1) * 8 + (l & 7);
    const int b_ch   = (b_i >> 1) * 16;

    float Oacc[8][4];
    #pragma unroll
    for (int nt = 0; nt < 8; ++nt)
        #pragma unroll
        for (int e = 0; e < 4; ++e) Oacc[nt][e] = 0.0f;
    float rs1 = 0.0f, rs2 = 0.0f;            // running (rescaled) row sums
    float m1 = -3.0e38f, m2 = -3.0e38f;      // running row maxima

    for (int chunk = 0; chunk < NCHUNK; ++chunk) {
        CP_WAIT0();                // staging data arrived
        __syncthreads();           // + all warps done with prev GEMM2 (tiles free)

        // ---- convert staging fp32 -> K bf16 hi/lo, V fp16 tiles ----
        {
            const float4* stg = (const float4*)(smem + SM_STG);
            #pragma unroll
            for (int i = tid; i < CHUNK * 16; i += THREADS) {
                int t = i >> 4, d4 = i & 15;
                uint32_t off = swz((uint32_t)(t * 128 + d4 * 8));
                float4 kv = stg[i];
                uint32_t h0, l0, h1, l1;
                splitpack(kv.x, kv.y, h0, l0);
                splitpack(kv.z, kv.w, h1, l1);
                *(uint2*)(smem + SM_KH + off) = make_uint2(h0, h1);
                *(uint2*)(smem + SM_KL + off) = make_uint2(l0, l1);
                float4 vv = stg[1024 + i];
                *(uint2*)(smem + SM_VF + off) = make_uint2(packh2(vv.x, vv.y),
                                                           packh2(vv.z, vv.w));
            }
        }
        __syncthreads();           // tiles visible; staging reads complete

        // ---- prefetch next chunk (overlaps both GEMMs) ----
        if (chunk < NCHUNK - 1) {
            const uint32_t sg = sb + SM_STG;
            const int base = (chunk + 1) * 16384;
            #pragma unroll
            for (int j = 0; j < 4; ++j) {
                int off = tid * 16 + j * 4096;
                CP_ASYNC16(sg + off,         kg + base + off);
                CP_ASYNC16(sg + 16384 + off, vg + base + off);
            }
            CP_COMMIT();
        }

        // ---- GEMM1: S = Q @ K^T  [16 x 64] per warp, split-3 bf16 ----
        float acc[8][4];
        #pragma unroll
        for (int nt = 0; nt < 8; ++nt)
            #pragma unroll
            for (int e = 0; e < 4; ++e) acc[nt][e] = 0.0f;

        #pragma unroll
        for (int k16 = 0; k16 < 4; ++k16) {
            uint32_t Ah[4], Al[4];
            {
                uint32_t off = swz((uint32_t)((s0 + a_row) * 128 + k16 * 32 + a_kh * 16));
                LDSM_X4(Ah[0], Ah[1], Ah[2], Ah[3], sb + SM_QH + off);
                LDSM_X4(Al[0], Al[1], Al[2], Al[3], sb + SM_QL + off);
            }
            #pragma unroll
            for (int ntp = 0; ntp < 4; ++ntp) {
                uint32_t Bh[2][2], Bl[2][2];
                uint32_t off = swz((uint32_t)((ntp * 16 + b_nh + b_row) * 128 + k16 * 32 + b_kh));
                LDSM_X4(Bh[0][0], Bh[0][1], Bh[1][0], Bh[1][1], sb + SM_KH + off);
                LDSM_X4(Bl[0][0], Bl[0][1], Bl[1][0], Bl[1][1], sb + SM_KL + off);
                #pragma unroll
                for (int j = 0; j < 2; ++j) {
                    int nt = 2 * ntp + j;
                    mma_bf16(acc[nt], Ah, Bh[j]);
                    mma_bf16(acc[nt], Ah, Bl[j]);
                    mma_bf16(acc[nt], Al, Bh[j]);
                }
            }
        }

        // ---- mask + online max + exp -> fp16 P fragments ----
        #pragma unroll
        for (int nt = 0; nt < 8; ++nt)
            #pragma unroll
            for (int e = 0; e < 4; ++e) {
                float v = acc[nt][e];
                acc[nt][e] = (v == 0.0f) ? -100000.0f : v;
            }
        float cm1 = -3.0e38f, cm2 = -3.0e38f;
        #pragma unroll
        for (int nt = 0; nt < 8; ++nt) {
            cm1 = fmaxf(cm1, fmaxf(acc[nt][0], acc[nt][1]));
            cm2 = fmaxf(cm2, fmaxf(acc[nt][2], acc[nt][3]));
        }
        cm1 = fmaxf(cm1, __shfl_xor_sync(0xFFFFFFFFu, cm1, 1));
        cm1 = fmaxf(cm1, __shfl_xor_sync(0xFFFFFFFFu, cm1, 2));
        cm2 = fmaxf(cm2, __shfl_xor_sync(0xFFFFFFFFu, cm2, 1));
        cm2 = fmaxf(cm2, __shfl_xor_sync(0xFFFFFFFFu, cm2, 2));
        float nm1 = fmaxf(m1, cm1), nm2 = fmaxf(m2, cm2);
        float sc1 = __expf(m1 - nm1), sc2 = __expf(m2 - nm2);
        m1 = nm1; m2 = nm2;
        rs1 *= sc1; rs2 *= sc2;
        #pragma unroll
        for (int nt = 0; nt < 8; ++nt) {
            Oacc[nt][0] *= sc1; Oacc[nt][1] *= sc1;
            Oacc[nt][2] *= sc2; Oacc[nt][3] *= sc2;
        }

        uint32_t Pf[4][4];
        #pragma unroll
        for (int nt = 0; nt < 8; ++nt) {
            float e0 = __expf(acc[nt][0] - m1);
            float e1 = __expf(acc[nt][1] - m1);
            float e2 = __expf(acc[nt][2] - m2);
            float e3 = __expf(acc[nt][3] - m2);
            rs1 += e0 + e1;
            rs2 += e2 + e3;
            int kc = nt >> 1, j = nt & 1;
            Pf[kc][2 * j]     = packh2(e0, e1);
            Pf[kc][2 * j + 1] = packh2(e2, e3);
        }

        // ---- GEMM2: O += P @ V  [16 x 64] per warp, single fp16 ----
        #pragma unroll
        for (int k16 = 0; k16 < 4; ++k16) {
            #pragma unroll
            for (int ntp = 0; ntp < 4; ++ntp) {
                uint32_t Vf[2][2];
                uint32_t off = swz((uint32_t)((k16 * 16 + b_toff) * 128 + ntp * 32 + b_ch));
                LDSM_X4T(Vf[0][0], Vf[0][1], Vf[1][0], Vf[1][1], sb + SM_VF + off);
                mma_f16(Oacc[2 * ntp],     Pf[k16], Vf[0]);
                mma_f16(Oacc[2 * ntp + 1], Pf[k16], Vf[1]);
            }
        }
    }

    // ---- epilogue: reduce row sums across quad, normalize, store ----
    rs1 += __shfl_xor_sync(0xFFFFFFFFu, rs1, 1);
    rs1 += __shfl_xor_sync(0xFFFFFFFFu, rs1, 2);
    rs2 += __shfl_xor_sync(0xFFFFFFFFu, rs2, 1);
    rs2 += __shfl_xor_sync(0xFFFFFFFFu, rs2, 2);
    float inv1 = 1.0f / rs1;
    float inv2 = 1.0f / rs2;

    float* ob = out + (size_t)bw * (S_DIM * D_DIM);
    const int r1 = s0 + (l >> 2), r2 = r1 + 8;
    const int ec = (l & 3) * 2;
    #pragma unroll
    for (int nt = 0; nt < 8; ++nt) {
        int c = nt * 8 + ec;
        *(float2*)(ob + r1 * 64 + c) = make_float2(Oacc[nt][0] * inv1, Oacc[nt][1] * inv1);
        *(float2*)(ob + r2 * 64 + c) = make_float2(Oacc[nt][2] * inv2, Oacc[nt][3] * inv2);
    }
}

extern "C" void kernel_launch(void* const* d_in, const int* in_sizes, int n_in,
                              void* d_out, int out_size)
{
    const float* q    = (const float*)d_in[0];
    const float* keys = (const float*)d_in[1];
    const float* vals = (const float*)d_in[2];
    float* out = (float*)d_out;

    const int BW = in_sizes[1] / (T_DIM * D_DIM);   // 2048

    cudaFuncSetAttribute(attn_flash4_kernel,
                         cudaFuncAttributeMaxDynamicSharedMemorySize, SMEM_BYTES);
    attn_flash4_kernel<<<BW, THREADS, SMEM_BYTES>>>(q, keys, vals, out);
}

// round 8
// speedup vs baseline: 5.7415x; 1.0534x over previous
#include <cuda_runtime.h>
#include <cuda_bf16.h>
#include <cuda_fp16.h>
#include <cstdint>

// B*W = 2048 independent problems.
//   query  [S=128, D=64]  fp32 (shared)   keys/values [BW, T=256, D=64] fp32
//   out    [BW, S=128, D=64] fp32
#define S_DIM 128
#define D_DIM 64
#define T_DIM 256
#define CHUNK 64
#define NCHUNK (T_DIM / CHUNK)
#define THREADS 256

// smem (bytes): Q hi/lo bf16 + K hi/lo bf16 + V fp16 + fp32 staging
#define SM_QH   0                        // [128][64] bf16 = 16KB
#define SM_QL   16384
#define SM_KH   32768                    // [64][64] bf16 = 8KB
#define SM_KL   40960
#define SM_VF   49152                    // [64][64] fp16 = 8KB
#define SM_STG  57344                    // 32KB: K fp32 16KB + V fp32 16KB
#define SMEM_BYTES (SM_STG + 32768)      // 90112 (88KB) -> 2 CTAs/SM

__device__ __forceinline__ uint32_t smem_u32(const void* p) {
    uint32_t a;
    asm("{ .reg .u64 t; cvta.to.shared.u64 t, %1; cvt.u32.u64 %0, t; }" : "=r"(a) : "l"(p));
    return a;
}
__device__ __forceinline__ uint32_t swz(uint32_t b) { return b ^ ((b >> 3) & 0x70); }

#define CP_ASYNC16(SA, GA) \
    asm volatile("cp.async.cg.shared.global [%0], [%1], 16;" :: "r"(SA), "l"(GA) : "memory")
#define CP_COMMIT() asm volatile("cp.async.commit_group;" ::: "memory")
#define CP_WAIT0()  asm volatile("cp.async.wait_group 0;" ::: "memory")

// ---- cheap split: hi = truncated bf16 (packed via PRMT), lo = rn(residual) ----
__device__ __forceinline__ void splitpack_fast(float x, float y, uint32_t& hp, uint32_t& lp) {
    uint32_t xi = __float_as_uint(x), yi = __float_as_uint(y);
    hp = __byte_perm(xi, yi, 0x7632);                       // {y_hi16, x_hi16}
    float xh = __uint_as_float(xi & 0xFFFF0000u);
    float yh = __uint_as_float(yi & 0xFFFF0000u);
    __nv_bfloat162 p = __floats2bfloat162_rn(x - xh, y - yh);
    lp = *(uint32_t*)&p;
}
__device__ __forceinline__ uint32_t packh2(float a, float b) {
    __half2 p = __floats2half2_rn(a, b);
    return *(uint32_t*)&p;
}

#define LDSM_X4(R0,R1,R2,R3,A) \
    asm volatile("ldmatrix.sync.aligned.m8n8.x4.shared.b16 {%0,%1,%2,%3}, [%4];" \
        : "=r"(R0),"=r"(R1),"=r"(R2),"=r"(R3) : "r"(A))
#define LDSM_X4T(R0,R1,R2,R3,A) \
    asm volatile("ldmatrix.sync.aligned.m8n8.x4.trans.shared.b16 {%0,%1,%2,%3}, [%4];" \
        : "=r"(R0),"=r"(R1),"=r"(R2),"=r"(R3) : "r"(A))

__device__ __forceinline__ void mma_bf16(float c[4], const uint32_t a[4], const uint32_t b[2]) {
    asm volatile("mma.sync.aligned.m16n8k16.row.col.f32.bf16.bf16.f32 "
        "{%0,%1,%2,%3}, {%4,%5,%6,%7}, {%8,%9}, {%0,%1,%2,%3};"
        : "+f"(c[0]), "+f"(c[1]), "+f"(c[2]), "+f"(c[3])
        : "r"(a[0]), "r"(a[1]), "r"(a[2]), "r"(a[3]), "r"(b[0]), "r"(b[1]));
}
__device__ __forceinline__ void mma_f16(float c[4], const uint32_t a[4], const uint32_t b[2]) {
    asm volatile("mma.sync.aligned.m16n8k16.row.col.f32.f16.f16.f32 "
        "{%0,%1,%2,%3}, {%4,%5,%6,%7}, {%8,%9}, {%0,%1,%2,%3};"
        : "+f"(c[0]), "+f"(c[1]), "+f"(c[2]), "+f"(c[3])
        : "r"(a[0]), "r"(a[1]), "r"(a[2]), "r"(a[3]), "r"(b[0]), "r"(b[1]));
}

__global__ void __launch_bounds__(THREADS, 2)
attn_flash5_kernel(const float* __restrict__ q,
                   const float* __restrict__ keys,
                   const float* __restrict__ values,
                   float* __restrict__ out)
{
    extern __shared__ char smem[];
    const uint32_t sb = smem_u32(smem);
    const int tid = threadIdx.x;
    const int w   = tid >> 5;
    const int l   = tid & 31;
    const int bw  = blockIdx.x;
    const int s0  = w * 16;

    const char* kg = (const char*)(keys   + (size_t)bw * T_DIM * D_DIM);
    const char* vg = (const char*)(values + (size_t)bw * T_DIM * D_DIM);

    // ---- prefetch chunk 0 (16B cp.async, bypasses RF) ----
    {
        const uint32_t sg = sb + SM_STG;
        #pragma unroll
        for (int j = 0; j < 4; ++j) {
            int off = tid * 16 + j * 4096;
            CP_ASYNC16(sg + off,         kg + off);
            CP_ASYNC16(sg + 16384 + off, vg + off);
        }
        CP_COMMIT();
    }

    // ---- convert Q -> smem bf16 hi/lo (overlaps with cp.async) ----
    {
        const float4* q4 = (const float4*)q;
        #pragma unroll
        for (int i = tid; i < S_DIM * 16; i += THREADS) {
            int s = i >> 4, d4 = i & 15;
            uint32_t off = swz((uint32_t)(s * 128 + d4 * 8));
            float4 v = q4[i];
            uint32_t h0, l0, h1, l1;
            splitpack_fast(v.x, v.y, h0, l0);
            splitpack_fast(v.z, v.w, h1, l1);
            *(uint2*)(smem + SM_QH + off) = make_uint2(h0, h1);
            *(uint2*)(smem + SM_QL + off) = make_uint2(l0, l1);
        }
    }

    // ldmatrix lane patterns
    const int a_row  = l & 15;
    const int a_kh   = l >> 4;
    const int b_i    = l >> 3;
    const int b_row  = l & 7;
    const int b_nh   = (b_i >> 1) * 8;
    const int b_kh   = (b_i & 1) * 16;
    const int b_toff = (b_i & 1) * 8 + (l & 7);
    const int b_ch   = (b_i >> 1) * 16;

    float Oacc[8][4];
    #pragma unroll
    for (int nt = 0; nt < 8; ++nt)
        #pragma unroll
        for (int e = 0; e < 4; ++e) Oacc[nt][e] = 0.0f;
    float rs1 = 0.0f, rs2 = 0.0f;            // running (rescaled) row sums
    float m1 = -3.0e38f, m2 = -3.0e38f;      // running row maxima

    for (int chunk = 0; chunk < NCHUNK; ++chunk) {
        CP_WAIT0();                // staging data arrived
        __syncthreads();           // + all warps done with prev GEMM2 (tiles free)

        // ---- convert staging fp32 -> K bf16 hi/lo, V fp16 tiles ----
        {
            const float4* stg = (const float4*)(smem + SM_STG);
            #pragma unroll
            for (int i = tid; i < CHUNK * 16; i += THREADS) {
                int t = i >> 4, d4 = i & 15;
                uint32_t off = swz((uint32_t)(t * 128 + d4 * 8));
                float4 kv = stg[i];
                uint32_t h0, l0, h1, l1;
                splitpack_fast(kv.x, kv.y, h0, l0);
                splitpack_fast(kv.z, kv.w, h1, l1);
                *(uint2*)(smem + SM_KH + off) = make_uint2(h0, h1);
                *(uint2*)(smem + SM_KL + off) = make_uint2(l0, l1);
                float4 vv = stg[1024 + i];
                *(uint2*)(smem + SM_VF + off) = make_uint2(packh2(vv.x, vv.y),
                                                           packh2(vv.z, vv.w));
            }
        }
        __syncthreads();           // tiles visible; staging reads complete

        // ---- prefetch next chunk (overlaps both GEMMs) ----
        if (chunk < NCHUNK - 1) {
            const uint32_t sg = sb + SM_STG;
            const int base = (chunk + 1) * 16384;
            #pragma unroll
            for (int j = 0; j < 4; ++j) {
                int off = tid * 16 + j * 4096;
                CP_ASYNC16(sg + off,         kg + base + off);
                CP_ASYNC16(sg + 16384 + off, vg + base + off);
            }
            CP_COMMIT();
        }

        // ---- GEMM1: S = Q @ K^T  [16 x 64] per warp, split-3 bf16 ----
        float acc[8][4];
        #pragma unroll
        for (int nt = 0; nt < 8; ++nt)
            #pragma unroll
            for (int e = 0; e < 4; ++e) acc[nt][e] = 0.0f;

        #pragma unroll
        for (int k16 = 0; k16 < 4; ++k16) {
            uint32_t Ah[4], Al[4];
            {
                uint32_t off = swz((uint32_t)((s0 + a_row) * 128 + k16 * 32 + a_kh * 16));
                LDSM_X4(Ah[0], Ah[1], Ah[2], Ah[3], sb + SM_QH + off);
                LDSM_X4(Al[0], Al[1], Al[2], Al[3], sb + SM_QL + off);
            }
            #pragma unroll
            for (int ntp = 0; ntp < 4; ++ntp) {
                uint32_t Bh[2][2], Bl[2][2];
                uint32_t off = swz((uint32_t)((ntp * 16 + b_nh + b_row) * 128 + k16 * 32 + b_kh));
                LDSM_X4(Bh[0][0], Bh[0][1], Bh[1][0], Bh[1][1], sb + SM_KH + off);
                LDSM_X4(Bl[0][0], Bl[0][1], Bl[1][0], Bl[1][1], sb + SM_KL + off);
                #pragma unroll
                for (int j = 0; j < 2; ++j) {
                    int nt = 2 * ntp + j;
                    mma_bf16(acc[nt], Ah, Bh[j]);
                    mma_bf16(acc[nt], Ah, Bl[j]);
                    mma_bf16(acc[nt], Al, Bh[j]);
                }
            }
        }

        // ---- mask + online max + exp -> fp16 P fragments ----
        #pragma unroll
        for (int nt = 0; nt < 8; ++nt)
            #pragma unroll
            for (int e = 0; e < 4; ++e) {
                float v = acc[nt][e];
                acc[nt][e] = (v == 0.0f) ? -100000.0f : v;
            }
        float cm1 = -3.0e38f, cm2 = -3.0e38f;
        #pragma unroll
        for (int nt = 0; nt < 8; ++nt) {
            cm1 = fmaxf(cm1, fmaxf(acc[nt][0], acc[nt][1]));
            cm2 = fmaxf(cm2, fmaxf(acc[nt][2], acc[nt][3]));
        }
        cm1 = fmaxf(cm1, __shfl_xor_sync(0xFFFFFFFFu, cm1, 1));
        cm1 = fmaxf(cm1, __shfl_xor_sync(0xFFFFFFFFu, cm1, 2));
        cm2 = fmaxf(cm2, __shfl_xor_sync(0xFFFFFFFFu, cm2, 1));
        cm2 = fmaxf(cm2, __shfl_xor_sync(0xFFFFFFFFu, cm2, 2));

        // conditional rescale: skip when no lane's row max changed
        bool nochg = (cm1 <= m1) & (cm2 <= m2);
        if (!__all_sync(0xFFFFFFFFu, nochg)) {
            float nm1 = fmaxf(m1, cm1), nm2 = fmaxf(m2, cm2);
            float sc1 = __expf(m1 - nm1), sc2 = __expf(m2 - nm2);
            m1 = nm1; m2 = nm2;
            rs1 *= sc1; rs2 *= sc2;
            #pragma unroll
            for (int nt = 0; nt < 8; ++nt) {
                Oacc[nt][0] *= sc1; Oacc[nt][1] *= sc1;
                Oacc[nt][2] *= sc2; Oacc[nt][3] *= sc2;
            }
        }

        uint32_t Pf[4][4];
        #pragma unroll
        for (int nt = 0; nt < 8; ++nt) {
            float e0 = __expf(acc[nt][0] - m1);
            float e1 = __expf(acc[nt][1] - m1);
            float e2 = __expf(acc[nt][2] - m2);
            float e3 = __expf(acc[nt][3] - m2);
            rs1 += e0 + e1;
            rs2 += e2 + e3;
            int kc = nt >> 1, j = nt & 1;
            Pf[kc][2 * j]     = packh2(e0, e1);
            Pf[kc][2 * j + 1] = packh2(e2, e3);
        }

        // ---- GEMM2: O += P @ V  [16 x 64] per warp, single fp16 ----
        #pragma unroll
        for (int k16 = 0; k16 < 4; ++k16) {
            #pragma unroll
            for (int ntp = 0; ntp < 4; ++ntp) {
                uint32_t Vf[2][2];
                uint32_t off = swz((uint32_t)((k16 * 16 + b_toff) * 128 + ntp * 32 + b_ch));
                LDSM_X4T(Vf[0][0], Vf[0][1], Vf[1][0], Vf[1][1], sb + SM_VF + off);
                mma_f16(Oacc[2 * ntp],     Pf[k16], Vf[0]);
                mma_f16(Oacc[2 * ntp + 1], Pf[k16], Vf[1]);
            }
        }
    }

    // ---- epilogue: reduce row sums across quad, normalize, store ----
    rs1 += __shfl_xor_sync(0xFFFFFFFFu, rs1, 1);
    rs1 += __shfl_xor_sync(0xFFFFFFFFu, rs1, 2);
    rs2 += __shfl_xor_sync(0xFFFFFFFFu, rs2, 1);
    rs2 += __shfl_xor_sync(0xFFFFFFFFu, rs2, 2);
    float inv1 = 1.0f / rs1;
    float inv2 = 1.0f / rs2;

    float* ob = out + (size_t)bw * (S_DIM * D_DIM);
    const int r1 = s0 + (l >> 2), r2 = r1 + 8;
    const int ec = (l & 3) * 2;
    #pragma unroll
    for (int nt = 0; nt < 8; ++nt) {
        int c = nt * 8 + ec;
        *(float2*)(ob + r1 * 64 + c) = make_float2(Oacc[nt][0] * inv1, Oacc[nt][1] * inv1);
        *(float2*)(ob + r2 * 64 + c) = make_float2(Oacc[nt][2] * inv2, Oacc[nt][3] * inv2);
    }
}

extern "C" void kernel_launch(void* const* d_in, const int* in_sizes, int n_in,
                              void* d_out, int out_size)
{
    const float* q    = (const float*)d_in[0];
    const float* keys = (const float*)d_in[1];
    const float* vals = (const float*)d_in[2];
    float* out = (float*)d_out;

    const int BW = in_sizes[1] / (T_DIM * D_DIM);   // 2048

    cudaFuncSetAttribute(attn_flash5_kernel,
                         cudaFuncAttributeMaxDynamicSharedMemorySize, SMEM_BYTES);
    attn_flash5_kernel<<<BW, THREADS, SMEM_BYTES>>>(q, keys, vals, out);
}

// round 9
// speedup vs baseline: 5.8232x; 1.0142x over previous
#include <cuda_runtime.h>
#include <cuda_bf16.h>
#include <cuda_fp16.h>
#include <cstdint>

// B*W = 2048 independent problems.
//   query  [S=128, D=64]  fp32 (shared)   keys/values [BW, T=256, D=64] fp32
//   out    [BW, S=128, D=64] fp32
#define S_DIM 128
#define D_DIM 64
#define T_DIM 256
#define CHUNK 64
#define NCHUNK (T_DIM / CHUNK)
#define THREADS 256

// smem (bytes): Q hi/lo bf16 + K hi/lo bf16 + V fp16 + fp32 staging
#define SM_QH   0                        // [128][64] bf16 = 16KB
#define SM_QL   16384
#define SM_KH   32768                    // [64][64] bf16 = 8KB
#define SM_KL   40960
#define SM_VF   49152                    // [64][64] fp16 = 8KB
#define SM_STG  57344                    // 32KB: K fp32 16KB + V fp32 16KB
#define SMEM_BYTES (SM_STG + 32768)      // 90112 (88KB) -> 2 CTAs/SM

#define L2E 1.4426950408889634f

__device__ __forceinline__ uint32_t smem_u32(const void* p) {
    uint32_t a;
    asm("{ .reg .u64 t; cvta.to.shared.u64 t, %1; cvt.u32.u64 %0, t; }" : "=r"(a) : "l"(p));
    return a;
}
__device__ __forceinline__ uint32_t swz(uint32_t b) { return b ^ ((b >> 3) & 0x70); }

#define CP_ASYNC16(SA, GA) \
    asm volatile("cp.async.cg.shared.global [%0], [%1], 16;" :: "r"(SA), "l"(GA) : "memory")
#define CP_COMMIT() asm volatile("cp.async.commit_group;" ::: "memory")
#define CP_WAIT0()  asm volatile("cp.async.wait_group 0;" ::: "memory")

// ---- cheap split: hi = truncated bf16 (packed via PRMT), lo = rn(residual) ----
__device__ __forceinline__ void splitpack_fast(float x, float y, uint32_t& hp, uint32_t& lp) {
    uint32_t xi = __float_as_uint(x), yi = __float_as_uint(y);
    hp = __byte_perm(xi, yi, 0x7632);                       // {y_hi16, x_hi16}
    float xh = __uint_as_float(xi & 0xFFFF0000u);
    float yh = __uint_as_float(yi & 0xFFFF0000u);
    __nv_bfloat162 p = __floats2bfloat162_rn(x - xh, y - yh);
    lp = *(uint32_t*)&p;
}
__device__ __forceinline__ uint32_t packh2(float a, float b) {
    __half2 p = __floats2half2_rn(a, b);
    return *(uint32_t*)&p;
}
// packed 2^((a - m)·log2e) in fp16x2; mlog = -m*L2E precomputed
__device__ __forceinline__ uint32_t ex2h2(float a, float b, float mlog) {
    float xa = fmaf(a, L2E, mlog);
    float xb = fmaf(b, L2E, mlog);
    uint32_t r = packh2(xa, xb), o;
    asm("ex2.approx.f16x2 %0, %1;" : "=r"(o) : "r"(r));
    return o;
}

#define LDSM_X4(R0,R1,R2,R3,A) \
    asm volatile("ldmatrix.sync.aligned.m8n8.x4.shared.b16 {%0,%1,%2,%3}, [%4];" \
        : "=r"(R0),"=r"(R1),"=r"(R2),"=r"(R3) : "r"(A))
#define LDSM_X4T(R0,R1,R2,R3,A) \
    asm volatile("ldmatrix.sync.aligned.m8n8.x4.trans.shared.b16 {%0,%1,%2,%3}, [%4];" \
        : "=r"(R0),"=r"(R1),"=r"(R2),"=r"(R3) : "r"(A))

__device__ __forceinline__ void mma_bf16(float c[4], const uint32_t a[4], const uint32_t b[2]) {
    asm volatile("mma.sync.aligned.m16n8k16.row.col.f32.bf16.bf16.f32 "
        "{%0,%1,%2,%3}, {%4,%5,%6,%7}, {%8,%9}, {%0,%1,%2,%3};"
        : "+f"(c[0]), "+f"(c[1]), "+f"(c[2]), "+f"(c[3])
        : "r"(a[0]), "r"(a[1]), "r"(a[2]), "r"(a[3]), "r"(b[0]), "r"(b[1]));
}
__device__ __forceinline__ void mma_f16(float c[4], const uint32_t a[4], const uint32_t b[2]) {
    asm volatile("mma.sync.aligned.m16n8k16.row.col.f32.f16.f16.f32 "
        "{%0,%1,%2,%3}, {%4,%5,%6,%7}, {%8,%9}, {%0,%1,%2,%3};"
        : "+f"(c[0]), "+f"(c[1]), "+f"(c[2]), "+f"(c[3])
        : "r"(a[0]), "r"(a[1]), "r"(a[2]), "r"(a[3]), "r"(b[0]), "r"(b[1]));
}

__global__ void __launch_bounds__(THREADS, 2)
attn_flash6_kernel(const float* __restrict__ q,
                   const float* __restrict__ keys,
                   const float* __restrict__ values,
                   float* __restrict__ out)
{
    extern __shared__ char smem[];
    const uint32_t sb = smem_u32(smem);
    const int tid = threadIdx.x;
    const int w   = tid >> 5;
    const int l   = tid & 31;
    const int bw  = blockIdx.x;
    const int s0  = w * 16;

    const char* kg = (const char*)(keys   + (size_t)bw * T_DIM * D_DIM);
    const char* vg = (const char*)(values + (size_t)bw * T_DIM * D_DIM);

    // ---- prefetch chunk 0 (16B cp.async, bypasses RF) ----
    {
        const uint32_t sg = sb + SM_STG;
        #pragma unroll
        for (int j = 0; j < 4; ++j) {
            int off = tid * 16 + j * 4096;
            CP_ASYNC16(sg + off,         kg + off);
            CP_ASYNC16(sg + 16384 + off, vg + off);
        }
        CP_COMMIT();
    }

    // ---- convert Q -> smem bf16 hi/lo (16B stores; overlaps cp.async) ----
    {
        const float4* q4 = (const float4*)q;
        #pragma unroll
        for (int i = tid; i < S_DIM * 8; i += THREADS) {
            int s = i >> 3, d8 = i & 7;
            uint32_t off = swz((uint32_t)(s * 128 + d8 * 16));
            float4 a = q4[s * 16 + d8 * 2];
            float4 b = q4[s * 16 + d8 * 2 + 1];
            uint32_t h0,l0,h1,l1,h2,l2,h3,l3;
            splitpack_fast(a.x, a.y, h0, l0);
            splitpack_fast(a.z, a.w, h1, l1);
            splitpack_fast(b.x, b.y, h2, l2);
            splitpack_fast(b.z, b.w, h3, l3);
            *(uint4*)(smem + SM_QH + off) = make_uint4(h0, h1, h2, h3);
            *(uint4*)(smem + SM_QL + off) = make_uint4(l0, l1, l2, l3);
        }
    }

    // ldmatrix lane patterns
    const int a_row  = l & 15;
    const int a_kh   = l >> 4;
    const int b_i    = l >> 3;
    const int b_row  = l & 7;
    const int b_nh   = (b_i >> 1) * 8;
    const int b_kh   = (b_i & 1) * 16;
    const int b_toff = (b_i & 1) * 8 + (l & 7);
    const int b_ch   = (b_i >> 1) * 16;

    float Oacc[8][4];
    #pragma unroll
    for (int nt = 0; nt < 8; ++nt)
        #pragma unroll
        for (int e = 0; e < 4; ++e) Oacc[nt][e] = 0.0f;
    float c_rs[4] = {0.0f, 0.0f, 0.0f, 0.0f};   // row sums via ones-MMA
    const uint32_t onesb[2] = {0x3C003C00u, 0x3C003C00u};
    float m1 = -3.0e38f, m2 = -3.0e38f;          // running row maxima

    for (int chunk = 0; chunk < NCHUNK; ++chunk) {
        CP_WAIT0();                // staging data arrived
        __syncthreads();           // + all warps done with prev GEMM2 (tiles free)

        // ---- convert staging fp32 -> K bf16 hi/lo, V fp16 (16B stores) ----
        {
            const float4* stg = (const float4*)(smem + SM_STG);
            #pragma unroll
            for (int i = tid; i < CHUNK * 8; i += THREADS) {
                int t = i >> 3, d8 = i & 7;
                uint32_t off = swz((uint32_t)(t * 128 + d8 * 16));
                float4 a = stg[t * 16 + d8 * 2];
                float4 b = stg[t * 16 + d8 * 2 + 1];
                uint32_t h0,l0,h1,l1,h2,l2,h3,l3;
                splitpack_fast(a.x, a.y, h0, l0);
                splitpack_fast(a.z, a.w, h1, l1);
                splitpack_fast(b.x, b.y, h2, l2);
                splitpack_fast(b.z, b.w, h3, l3);
                *(uint4*)(smem + SM_KH + off) = make_uint4(h0, h1, h2, h3);
                *(uint4*)(smem + SM_KL + off) = make_uint4(l0, l1, l2, l3);
                float4 va = stg[1024 + t * 16 + d8 * 2];
                float4 vb = stg[1024 + t * 16 + d8 * 2 + 1];
                *(uint4*)(smem + SM_VF + off) = make_uint4(packh2(va.x, va.y), packh2(va.z, va.w),
                                                           packh2(vb.x, vb.y), packh2(vb.z, vb.w));
            }
        }
        __syncthreads();           // tiles visible; staging reads complete

        // ---- prefetch next chunk (overlaps both GEMMs) ----
        if (chunk < NCHUNK - 1) {
            const uint32_t sg = sb + SM_STG;
            const int base = (chunk + 1) * 16384;
            #pragma unroll
            for (int j = 0; j < 4; ++j) {
                int off = tid * 16 + j * 4096;
                CP_ASYNC16(sg + off,         kg + base + off);
                CP_ASYNC16(sg + 16384 + off, vg + base + off);
            }
            CP_COMMIT();
        }

        // ---- GEMM1: S = Q @ K^T  [16 x 64] per warp, split-3 bf16 ----
        float acc[8][4];
        #pragma unroll
        for (int nt = 0; nt < 8; ++nt)
            #pragma unroll
            for (int e = 0; e < 4; ++e) acc[nt][e] = 0.0f;

        #pragma unroll
        for (int k16 = 0; k16 < 4; ++k16) {
            uint32_t Ah[4], Al[4];
            {
                uint32_t off = swz((uint32_t)((s0 + a_row) * 128 + k16 * 32 + a_kh * 16));
                LDSM_X4(Ah[0], Ah[1], Ah[2], Ah[3], sb + SM_QH + off);
                LDSM_X4(Al[0], Al[1], Al[2], Al[3], sb + SM_QL + off);
            }
            #pragma unroll
            for (int ntp = 0; ntp < 4; ++ntp) {
                uint32_t Bh[2][2], Bl[2][2];
                uint32_t off = swz((uint32_t)((ntp * 16 + b_nh + b_row) * 128 + k16 * 32 + b_kh));
                LDSM_X4(Bh[0][0], Bh[0][1], Bh[1][0], Bh[1][1], sb + SM_KH + off);
                LDSM_X4(Bl[0][0], Bl[0][1], Bl[1][0], Bl[1][1], sb + SM_KL + off);
                #pragma unroll
                for (int j = 0; j < 2; ++j) {
                    int nt = 2 * ntp + j;
                    mma_bf16(acc[nt], Ah, Bh[j]);
                    mma_bf16(acc[nt], Ah, Bl[j]);
                    mma_bf16(acc[nt], Al, Bh[j]);
                }
            }
        }

        // ---- mask + online max ----
        #pragma unroll
        for (int nt = 0; nt < 8; ++nt)
            #pragma unroll
            for (int e = 0; e < 4; ++e) {
                float v = acc[nt][e];
                acc[nt][e] = (v == 0.0f) ? -100000.0f : v;
            }
        float cm1 = -3.0e38f, cm2 = -3.0e38f;
        #pragma unroll
        for (int nt = 0; nt < 8; ++nt) {
            cm1 = fmaxf(cm1, fmaxf(acc[nt][0], acc[nt][1]));
            cm2 = fmaxf(cm2, fmaxf(acc[nt][2], acc[nt][3]));
        }
        cm1 = fmaxf(cm1, __shfl_xor_sync(0xFFFFFFFFu, cm1, 1));
        cm1 = fmaxf(cm1, __shfl_xor_sync(0xFFFFFFFFu, cm1, 2));
        cm2 = fmaxf(cm2, __shfl_xor_sync(0xFFFFFFFFu, cm2, 1));
        cm2 = fmaxf(cm2, __shfl_xor_sync(0xFFFFFFFFu, cm2, 2));

        // conditional rescale: skip when no lane's row max changed
        bool nochg = (cm1 <= m1) & (cm2 <= m2);
        if (!__all_sync(0xFFFFFFFFu, nochg)) {
            float nm1 = fmaxf(m1, cm1), nm2 = fmaxf(m2, cm2);
            float sc1 = __expf(m1 - nm1), sc2 = __expf(m2 - nm2);
            m1 = nm1; m2 = nm2;
            c_rs[0] *= sc1; c_rs[1] *= sc1;
            c_rs[2] *= sc2; c_rs[3] *= sc2;
            #pragma unroll
            for (int nt = 0; nt < 8; ++nt) {
                Oacc[nt][0] *= sc1; Oacc[nt][1] *= sc1;
                Oacc[nt][2] *= sc2; Oacc[nt][3] *= sc2;
            }
        }

        // ---- exp directly into packed fp16 P fragments ----
        const float mlog1 = -m1 * L2E, mlog2 = -m2 * L2E;
        uint32_t Pf[4][4];
        #pragma unroll
        for (int nt = 0; nt < 8; ++nt) {
            int kc = nt >> 1, j = nt & 1;
            Pf[kc][2 * j]     = ex2h2(acc[nt][0], acc[nt][1], mlog1);
            Pf[kc][2 * j + 1] = ex2h2(acc[nt][2], acc[nt][3], mlog2);
        }
        // row sums: rs += P @ ones  (consistent with GEMM2's quantized P)
        #pragma unroll
        for (int kc = 0; kc < 4; ++kc) mma_f16(c_rs, Pf[kc], onesb);

        // ---- GEMM2: O += P @ V  [16 x 64] per warp, single fp16 ----
        #pragma unroll
        for (int k16 = 0; k16 < 4; ++k16) {
            #pragma unroll
            for (int ntp = 0; ntp < 4; ++ntp) {
                uint32_t Vf[2][2];
                uint32_t off = swz((uint32_t)((k16 * 16 + b_toff) * 128 + ntp * 32 + b_ch));
                LDSM_X4T(Vf[0][0], Vf[0][1], Vf[1][0], Vf[1][1], sb + SM_VF + off);
                mma_f16(Oacc[2 * ntp],     Pf[k16], Vf[0]);
                mma_f16(Oacc[2 * ntp + 1], Pf[k16], Vf[1]);
            }
        }
    }

    // ---- epilogue: normalize by ones-MMA row sums, store ----
    float inv1 = 1.0f / c_rs[0];
    float inv2 = 1.0f / c_rs[2];

    float* ob = out + (size_t)bw * (S_DIM * D_DIM);
    const int r1 = s0 + (l >> 2), r2 = r1 + 8;
    const int ec = (l & 3) * 2;
    #pragma unroll
    for (int nt = 0; nt < 8; ++nt) {
        int c = nt * 8 + ec;
        *(float2*)(ob + r1 * 64 + c) = make_float2(Oacc[nt][0] * inv1, Oacc[nt][1] * inv1);
        *(float2*)(ob + r2 * 64 + c) = make_float2(Oacc[nt][2] * inv2, Oacc[nt][3] * inv2);
    }
}

extern "C" void kernel_launch(void* const* d_in, const int* in_sizes, int n_in,
                              void* d_out, int out_size)
{
    const float* q    = (const float*)d_in[0];
    const float* keys = (const float*)d_in[1];
    const float* vals = (const float*)d_in[2];
    float* out = (float*)d_out;

    const int BW = in_sizes[1] / (T_DIM * D_DIM);   // 2048

    cudaFuncSetAttribute(attn_flash6_kernel,
                         cudaFuncAttributeMaxDynamicSharedMemorySize, SMEM_BYTES);
    attn_flash6_kernel<<<BW, THREADS, SMEM_BYTES>>>(q, keys, vals, out);
}